// round 1
// baseline (speedup 1.0000x reference)
#include <cuda_runtime.h>
#include <cstdint>
#include <cstddef>

#define DEV_INLINE __device__ __forceinline__

constexpr int B_  = 32;
constexpr int T_  = 1500;
constexpr int A_  = 512;
constexpr int E_  = 512;
constexpr int H_  = 512;
constexpr int V_  = 10000;
constexpr int LQ  = 101;    // L+1
constexpr int G4H = 2048;   // 4*H

// ---------------- device scratch (static, allowed) ----------------
__device__ float g_P[(size_t)B_ * T_ * A_];          // enc_proj  (98.3 MB)
__device__ float g_emb[(size_t)B_ * LQ * E_];        // gathered embeddings
__device__ float g_embg[(size_t)B_ * LQ * G4H];      // emb-part of gates + bias
__device__ float g_zc[(size_t)B_ * LQ * (H_ + A_)];  // [dec_z | c] per (b,t)
__device__ float g_WencT[A_ * A_];                   // W_enc transposed [a][d]
__device__ float g_Wrec[(size_t)G4H * 1024];         // [W_ih(:,512:1024) | W_hh] per row j
__device__ float g_bias[G4H];                        // b_ih + b_hh
__device__ float g_decz[B_ * H_];
__device__ float g_decc[B_ * H_];
__device__ float g_cvec[B_ * A_];
__device__ float g_q[B_ * A_];
__device__ float g_gpart[8 * B_ * G4H];              // split-K partials of recurrent gates
__device__ float g_e[B_ * T_];
__device__ float g_w[B_ * T_];

// ---------------- f32x2 helpers (sm_100+ packed fp32 FMA) ----------------
DEV_INLINE unsigned long long pack2(float x, float y) {
    unsigned long long r;
    asm("mov.b64 %0, {%1, %2};" : "=l"(r) : "f"(x), "f"(y));
    return r;
}
DEV_INLINE void ffma2(unsigned long long& acc, unsigned long long a2, unsigned long long b2) {
    asm("fma.rn.f32x2 %0, %1, %2, %0;" : "+l"(acc) : "l"(a2), "l"(b2));
}
DEV_INLINE float lo32(unsigned long long v) { return __uint_as_float((unsigned)(v & 0xffffffffull)); }
DEV_INLINE float hi32(unsigned long long v) { return __uint_as_float((unsigned)(v >> 32)); }

DEV_INLINE float fast_tanh(float x) {
    x = fminf(fmaxf(x, -9.f), 9.f);
    float t = __expf(2.f * x);
    return __fdividef(t - 1.f, t + 1.f);
}
DEV_INLINE float sig_acc(float x) {            // accurate sigmoid for the recurrence
    return 1.f / (1.f + expf(-x));
}

// ---------------- setup kernels ----------------
__global__ void init_state_kernel() {
    int i = blockIdx.x * blockDim.x + threadIdx.x;
    if (i < B_ * H_) { g_decz[i] = 0.f; g_decc[i] = 0.f; g_cvec[i] = 0.f; }
}

__global__ void transpose_wenc_kernel(const float* __restrict__ W) {
    int idx = blockIdx.x * 256 + threadIdx.x;
    if (idx < 512 * 512) {
        int d = idx >> 9, a = idx & 511;
        g_WencT[a * 512 + d] = W[idx];
    }
}

__global__ void pack_wrec_kernel(const float* __restrict__ W_ih, const float* __restrict__ W_hh,
                                 const float* __restrict__ b_ih, const float* __restrict__ b_hh) {
    int idx = blockIdx.x * 256 + threadIdx.x;
    if (idx < G4H * 1024) {
        int j = idx >> 10, k = idx & 1023;
        g_Wrec[idx] = (k < 512) ? W_ih[(size_t)j * 1024 + 512 + k]
                                : W_hh[(size_t)j * 512 + (k - 512)];
    }
    if (idx < G4H) g_bias[idx] = b_ih[idx] + b_hh[idx];
}

__global__ void gather_emb_kernel(const int* __restrict__ ys, const float* __restrict__ emb) {
    int m = blockIdx.x;                 // m = b*101 + t
    int b = m / LQ, t = m % LQ;
    int idx = (t == 0) ? 1 : ys[b * 100 + t - 1];   // BOS=1
    const float* src = &emb[(size_t)idx * 512];
    float* dst = &g_emb[(size_t)m * 512];
    for (int k = threadIdx.x; k < 512; k += 128) dst[k] = src[k];
}

// ---------------- generic NT SGEMM: C[M,N] = A[M,K] * B[N,K]^T (+bias) ----------------
// 128x128 tile, BK=16, 256 threads, 8x8 micro-tile, f32x2 packed FMA.
__global__ void __launch_bounds__(256) sgemm_nt(
    const float* __restrict__ A, int lda,
    const float* __restrict__ Bm, int ldb,
    const float* __restrict__ bias,
    float* __restrict__ C, int ldc,
    int M, int N, int K)
{
    __shared__ float As[16][132];
    __shared__ float Bs[16][132];

    int tid = threadIdx.x;
    int row0 = blockIdx.y * 128, col0 = blockIdx.x * 128;
    int lr = tid >> 1;              // 0..127
    int lc = (tid & 1) * 8;         // 0 or 8
    int ty = tid >> 4, tx = tid & 15;

    unsigned long long acc[8][4];
#pragma unroll
    for (int i = 0; i < 8; i++)
#pragma unroll
        for (int j = 0; j < 4; j++) acc[i][j] = 0ull;

    for (int k0 = 0; k0 < K; k0 += 16) {
        float4 z4 = make_float4(0.f, 0.f, 0.f, 0.f);
        float4 a0 = z4, a1 = z4, b0 = z4, b1 = z4;
        int ar = row0 + lr;
        if (ar < M) {
            const float* ap = &A[(size_t)ar * lda + k0 + lc];
            a0 = *(const float4*)ap; a1 = *(const float4*)(ap + 4);
        }
        int br = col0 + lr;
        if (br < N) {
            const float* bp = &Bm[(size_t)br * ldb + k0 + lc];
            b0 = *(const float4*)bp; b1 = *(const float4*)(bp + 4);
        }
        As[lc + 0][lr] = a0.x; As[lc + 1][lr] = a0.y; As[lc + 2][lr] = a0.z; As[lc + 3][lr] = a0.w;
        As[lc + 4][lr] = a1.x; As[lc + 5][lr] = a1.y; As[lc + 6][lr] = a1.z; As[lc + 7][lr] = a1.w;
        Bs[lc + 0][lr] = b0.x; Bs[lc + 1][lr] = b0.y; Bs[lc + 2][lr] = b0.z; Bs[lc + 3][lr] = b0.w;
        Bs[lc + 4][lr] = b1.x; Bs[lc + 5][lr] = b1.y; Bs[lc + 6][lr] = b1.z; Bs[lc + 7][lr] = b1.w;
        __syncthreads();

#pragma unroll
        for (int kk = 0; kk < 16; kk++) {
            float afr[8], bfr[8];
            *(float4*)&afr[0] = *(const float4*)&As[kk][ty * 8];
            *(float4*)&afr[4] = *(const float4*)&As[kk][ty * 8 + 4];
            *(float4*)&bfr[0] = *(const float4*)&Bs[kk][tx * 8];
            *(float4*)&bfr[4] = *(const float4*)&Bs[kk][tx * 8 + 4];
            unsigned long long b2[4];
            b2[0] = pack2(bfr[0], bfr[1]); b2[1] = pack2(bfr[2], bfr[3]);
            b2[2] = pack2(bfr[4], bfr[5]); b2[3] = pack2(bfr[6], bfr[7]);
#pragma unroll
            for (int i = 0; i < 8; i++) {
                unsigned long long a2 = pack2(afr[i], afr[i]);
                ffma2(acc[i][0], a2, b2[0]);
                ffma2(acc[i][1], a2, b2[1]);
                ffma2(acc[i][2], a2, b2[2]);
                ffma2(acc[i][3], a2, b2[3]);
            }
        }
        __syncthreads();
    }

#pragma unroll
    for (int i = 0; i < 8; i++) {
        int r = row0 + ty * 8 + i;
        if (r >= M) continue;
        float* crow = C + (size_t)r * ldc;
#pragma unroll
        for (int j4 = 0; j4 < 4; j4++) {
            int c = col0 + tx * 8 + 2 * j4;
            float vlo = lo32(acc[i][j4]);
            float vhi = hi32(acc[i][j4]);
            if (c < N)     crow[c]     = vlo + (bias ? bias[c] : 0.f);
            if (c + 1 < N) crow[c + 1] = vhi + (bias ? bias[c + 1] : 0.f);
        }
    }
}

// ---------------- per-step recurrent gates (split-K) ----------------
// gates_rec[b,j] = sum_{k<512} c_prev[b,k]*Wrec[j,k] + sum_{k>=512} dec_z[b,k-512]*Wrec[j,k]
__global__ void __launch_bounds__(256) gates_kernel() {
    __shared__ float xh_s[32][36];
    __shared__ float w_s[32][132];
    int tid = threadIdx.x;
    int j0 = blockIdx.x * 128;
    int kz = blockIdx.y;        // 0..7, 128 K each
    int bq = tid & 7;           // b-group (4 b each)
    int jq = tid >> 3;          // j-group 0..31 (4 j each)

    unsigned long long acc[4][2];
#pragma unroll
    for (int i = 0; i < 4; i++) { acc[i][0] = 0ull; acc[i][1] = 0ull; }

    for (int kt0 = 0; kt0 < 128; kt0 += 32) {
        int kb = kz * 128 + kt0;
#pragma unroll
        for (int r = 0; r < 4; r++) {
            int lin = tid + r * 256;
            int kt = lin & 31, b = lin >> 5;
            int kk = kb + kt;
            xh_s[kt][b] = (kk < 512) ? g_cvec[b * 512 + kk] : g_decz[b * 512 + kk - 512];
        }
        {
            int jj = tid >> 1, kof = (tid & 1) * 16;
            const float* wp = &g_Wrec[(size_t)(j0 + jj) * 1024 + kb + kof];
#pragma unroll
            for (int q = 0; q < 4; q++) {
                float4 v = *(const float4*)(wp + q * 4);
                w_s[kof + q * 4 + 0][jj] = v.x; w_s[kof + q * 4 + 1][jj] = v.y;
                w_s[kof + q * 4 + 2][jj] = v.z; w_s[kof + q * 4 + 3][jj] = v.w;
            }
        }
        __syncthreads();
#pragma unroll
        for (int kt = 0; kt < 32; kt++) {
            float4 av = *(const float4*)&xh_s[kt][bq * 4];
            float4 wv = *(const float4*)&w_s[kt][jq * 4];
            unsigned long long w2a = pack2(wv.x, wv.y);
            unsigned long long w2b = pack2(wv.z, wv.w);
            unsigned long long a2;
            a2 = pack2(av.x, av.x); ffma2(acc[0][0], a2, w2a); ffma2(acc[0][1], a2, w2b);
            a2 = pack2(av.y, av.y); ffma2(acc[1][0], a2, w2a); ffma2(acc[1][1], a2, w2b);
            a2 = pack2(av.z, av.z); ffma2(acc[2][0], a2, w2a); ffma2(acc[2][1], a2, w2b);
            a2 = pack2(av.w, av.w); ffma2(acc[3][0], a2, w2a); ffma2(acc[3][1], a2, w2b);
        }
        __syncthreads();
    }
#pragma unroll
    for (int ib = 0; ib < 4; ib++) {
        int b = bq * 4 + ib;
        float* gp = &g_gpart[(size_t)kz * (B_ * G4H) + (size_t)b * G4H + j0 + jq * 4];
        gp[0] = lo32(acc[ib][0]); gp[1] = hi32(acc[ib][0]);
        gp[2] = lo32(acc[ib][1]); gp[3] = hi32(acc[ib][1]);
    }
}

// ---------------- per-step LSTM pointwise + q = dec_z @ W_dec ----------------
__global__ void __launch_bounds__(512) lstm_pw_q_kernel(const float* __restrict__ W_dec, int step) {
    __shared__ float z_s[4][512];
    int tid = threadIdx.x, bx = blockIdx.x;
#pragma unroll
    for (int sub = 0; sub < 4; sub++) {
        int b = bx * 4 + sub;
        size_t m = (size_t)b * LQ + step;
        const float* eg = &g_embg[m * G4H];
        float gi = eg[tid], gf = eg[512 + tid], gg = eg[1024 + tid], go = eg[1536 + tid];
#pragma unroll
        for (int kz = 0; kz < 8; kz++) {
            const float* gp = &g_gpart[(size_t)kz * (B_ * G4H) + (size_t)b * G4H];
            gi += gp[tid]; gf += gp[512 + tid]; gg += gp[1024 + tid]; go += gp[1536 + tid];
        }
        float cp = g_decc[b * 512 + tid];
        float cn = sig_acc(gf) * cp + sig_acc(gi) * tanhf(gg);
        float z  = sig_acc(go) * tanhf(cn);
        g_decc[b * 512 + tid] = cn;
        g_decz[b * 512 + tid] = z;
        g_zc[m * 1024 + tid] = z;
        z_s[sub][tid] = z;
    }
    __syncthreads();
    float q0 = 0.f, q1 = 0.f, q2 = 0.f, q3 = 0.f;
#pragma unroll 8
    for (int k = 0; k < 512; k++) {
        float wv = W_dec[(size_t)k * 512 + tid];
        q0 += z_s[0][k] * wv; q1 += z_s[1][k] * wv;
        q2 += z_s[2][k] * wv; q3 += z_s[3][k] * wv;
    }
    g_q[(bx * 4 + 0) * 512 + tid] = q0;
    g_q[(bx * 4 + 1) * 512 + tid] = q1;
    g_q[(bx * 4 + 2) * 512 + tid] = q2;
    g_q[(bx * 4 + 3) * 512 + tid] = q3;
}

// ---------------- per-step attention scores ----------------
__global__ void __launch_bounds__(256) attn_e_kernel(const int* __restrict__ enc_len,
                                                     const float* __restrict__ v_att) {
    int b = blockIdx.y;
    int len = enc_len[b];
    int t0 = blockIdx.x * 64;
    if (t0 >= len) return;
    __shared__ float q_s[512], v_s[512];
    for (int i = threadIdx.x; i < 512; i += 256) { q_s[i] = g_q[b * 512 + i]; v_s[i] = v_att[i]; }
    __syncthreads();
    int warp = threadIdx.x >> 5, lane = threadIdx.x & 31;
    for (int r = 0; r < 8; r++) {
        int t = t0 + warp * 8 + r;
        if (t >= len) break;
        const float* Pr = &g_P[((size_t)(b * T_ + t)) * 512];
        float s = 0.f;
#pragma unroll
        for (int i = 0; i < 16; i++) {
            int a = i * 32 + lane;
            s += v_s[a] * fast_tanh(Pr[a] + q_s[a]);
        }
#pragma unroll
        for (int off = 16; off; off >>= 1) s += __shfl_xor_sync(0xffffffffu, s, off);
        if (lane == 0) g_e[b * T_ + t] = s;
    }
}

// ---------------- per-step masked softmax + ws store ----------------
__global__ void __launch_bounds__(256) softmax_ws_kernel(const int* __restrict__ enc_len,
                                                         float* __restrict__ out_ws, int step) {
    int b = blockIdx.x, tid = threadIdx.x;
    int len = enc_len[b];
    __shared__ float sred[256];
    const float* eb = &g_e[b * T_];
    float mx = -3.4e38f;
    for (int t = tid; t < len; t += 256) mx = fmaxf(mx, eb[t]);
    sred[tid] = mx; __syncthreads();
    for (int off = 128; off; off >>= 1) {
        if (tid < off) sred[tid] = fmaxf(sred[tid], sred[tid + off]);
        __syncthreads();
    }
    mx = sred[0]; __syncthreads();
    float s = 0.f;
    for (int t = tid; t < len; t += 256) s += __expf(eb[t] - mx);
    sred[tid] = s; __syncthreads();
    for (int off = 128; off; off >>= 1) {
        if (tid < off) sred[tid] += sred[tid + off];
        __syncthreads();
    }
    float inv = 1.f / sred[0];
    float* wsrow = out_ws ? &out_ws[((size_t)b * LQ + step) * T_] : nullptr;
    for (int t = tid; t < T_; t += 256) {
        float w = (t < len) ? __expf(eb[t] - mx) * inv : 0.f;
        g_w[b * T_ + t] = w;
        if (wsrow) wsrow[t] = w;
    }
}

// ---------------- per-step context ----------------
__global__ void __launch_bounds__(128) context_kernel(const float* __restrict__ enc_pad,
                                                      const int* __restrict__ enc_len, int step) {
    int b = blockIdx.y;
    int a = blockIdx.x * 128 + threadIdx.x;
    int len = enc_len[b];
    __shared__ float w_s[256];
    float acc = 0.f;
    for (int t0 = 0; t0 < len; t0 += 256) {
        int nt = min(256, len - t0);
        __syncthreads();
        for (int i = threadIdx.x; i < nt; i += 128) w_s[i] = g_w[b * T_ + t0 + i];
        __syncthreads();
        const float* ep = enc_pad + ((size_t)(b * T_ + t0)) * 512 + a;
        int tt = 0;
        for (; tt + 4 <= nt; tt += 4) {
            acc += w_s[tt + 0] * ep[(size_t)(tt + 0) * 512];
            acc += w_s[tt + 1] * ep[(size_t)(tt + 1) * 512];
            acc += w_s[tt + 2] * ep[(size_t)(tt + 2) * 512];
            acc += w_s[tt + 3] * ep[(size_t)(tt + 3) * 512];
        }
        for (; tt < nt; tt++) acc += w_s[tt] * ep[(size_t)tt * 512];
    }
    g_cvec[b * 512 + a] = acc;
    g_zc[((size_t)(b * LQ + step)) * 1024 + 512 + a] = acc;
}

// ---------------- final epilogue: log_softmax gather + argmax ----------------
__global__ void __launch_bounds__(256) epilogue_kernel(const int* __restrict__ ys,
                                                       const float* __restrict__ logits,
                                                       float* __restrict__ out_ylp,
                                                       float* __restrict__ out_pred) {
    int m = blockIdx.x, tid = threadIdx.x;
    const float* row = logits + (size_t)m * V_;
    __shared__ float sv[256];
    __shared__ int si[256];
    float mx = -3.4e38f; int mi = 0;
    for (int v = tid; v < V_; v += 256) {
        float x = row[v];
        if (x > mx) { mx = x; mi = v; }
    }
    sv[tid] = mx; si[tid] = mi; __syncthreads();
    for (int off = 128; off; off >>= 1) {
        if (tid < off) {
            float xo = sv[tid + off]; int io = si[tid + off];
            if (xo > sv[tid] || (xo == sv[tid] && io < si[tid])) { sv[tid] = xo; si[tid] = io; }
        }
        __syncthreads();
    }
    mx = sv[0]; int argi = si[0]; __syncthreads();
    float s = 0.f;
    for (int v = tid; v < V_; v += 256) s += __expf(row[v] - mx);
    sv[tid] = s; __syncthreads();
    for (int off = 128; off; off >>= 1) {
        if (tid < off) sv[tid] += sv[tid + off];
        __syncthreads();
    }
    if (tid == 0) {
        int b = m / LQ, t = m % LQ;
        int yo = (t < 100) ? ys[b * 100 + t] : 2;   // EOS=2
        out_ylp[m]  = row[yo] - mx - logf(sv[0]);
        out_pred[m] = (float)argi;
    }
}

// ---------------- host launch ----------------
extern "C" void kernel_launch(void* const* d_in, const int* in_sizes, int n_in,
                              void* d_out, int out_size) {
    const float* enc_pad  = (const float*)d_in[0];
    const int*   enc_len  = (const int*)  d_in[1];
    const int*   ys       = (const int*)  d_in[2];
    const float* emb_tab  = (const float*)d_in[3];
    const float* W_ih     = (const float*)d_in[4];
    const float* W_hh     = (const float*)d_in[5];
    const float* b_ih     = (const float*)d_in[6];
    const float* b_hh     = (const float*)d_in[7];
    const float* W_enc    = (const float*)d_in[8];
    const float* W_dec    = (const float*)d_in[9];
    const float* v_att    = (const float*)d_in[10];
    const float* W_out    = (const float*)d_in[11];
    const float* b_out    = (const float*)d_in[12];
    (void)in_sizes; (void)n_in;

    float* out = (float*)d_out;
    const size_t n_logits = (size_t)B_ * LQ * V_;          // 32,320,000
    const size_t n_row    = (size_t)B_ * LQ;               // 3232
    const size_t n_full   = n_logits + 2 * n_row + (size_t)B_ * LQ * T_;
    bool full = ((size_t)out_size >= n_full);

    float* out_logits = out;
    float* out_ylp  = full ? out + n_logits            : nullptr;
    float* out_pred = full ? out + n_logits + n_row    : nullptr;
    float* out_ws   = full ? out + n_logits + 2*n_row  : nullptr;

    // device scratch addresses
    float *pP, *pEmb, *pEmbG, *pZC, *pWencT, *pBias;
    cudaGetSymbolAddress((void**)&pP,     g_P);
    cudaGetSymbolAddress((void**)&pEmb,   g_emb);
    cudaGetSymbolAddress((void**)&pEmbG,  g_embg);
    cudaGetSymbolAddress((void**)&pZC,    g_zc);
    cudaGetSymbolAddress((void**)&pWencT, g_WencT);
    cudaGetSymbolAddress((void**)&pBias,  g_bias);

    // setup
    init_state_kernel<<<(B_ * H_ + 255) / 256, 256>>>();
    transpose_wenc_kernel<<<(512 * 512 + 255) / 256, 256>>>(W_enc);
    pack_wrec_kernel<<<(G4H * 1024 + 255) / 256, 256>>>(W_ih, W_hh, b_ih, b_hh);
    gather_emb_kernel<<<B_ * LQ, 128>>>(ys, emb_tab);

    // enc_proj = enc_pad @ W_enc  (NT form via W_enc^T)
    {
        dim3 g((A_ + 127) / 128, (B_ * T_ + 127) / 128);
        sgemm_nt<<<g, 256>>>(enc_pad, A_, pWencT, A_, nullptr, pP, A_, B_ * T_, A_, A_);
    }
    // emb-part of gates (+combined bias)
    {
        dim3 g((G4H + 127) / 128, (B_ * LQ + 127) / 128);
        sgemm_nt<<<g, 256>>>(pEmb, E_, W_ih, E_ + A_, pBias, pEmbG, G4H, B_ * LQ, G4H, E_);
    }

    // sequential decode loop
    for (int t = 0; t < LQ; t++) {
        gates_kernel<<<dim3(16, 8), 256>>>();
        lstm_pw_q_kernel<<<8, 512>>>(W_dec, t);
        attn_e_kernel<<<dim3((T_ + 63) / 64, B_), 256>>>(enc_len, v_att);
        softmax_ws_kernel<<<B_, 256>>>(enc_len, out_ws, t);
        context_kernel<<<dim3(4, B_), 128>>>(enc_pad, enc_len, t);
    }

    // logits = [dec_z | c] @ W_out^T + b_out  -> directly into d_out
    {
        dim3 g((V_ + 127) / 128, (B_ * LQ + 127) / 128);
        sgemm_nt<<<g, 256>>>(pZC, H_ + A_, W_out, H_ + A_, b_out, out_logits, V_,
                             B_ * LQ, V_, H_ + A_);
    }
    if (full) {
        epilogue_kernel<<<B_ * LQ, 256>>>(ys, out_logits, out_ylp, out_pred);
    }
}

// round 2
// speedup vs baseline: 1.0222x; 1.0222x over previous
#include <cuda_runtime.h>
#include <cstdint>
#include <cstddef>

#define DEV_INLINE __device__ __forceinline__

constexpr int B_  = 32;
constexpr int T_  = 1500;
constexpr int A_  = 512;
constexpr int E_  = 512;
constexpr int H_  = 512;
constexpr int V_  = 10000;
constexpr int LQ  = 101;    // L+1
constexpr int G4H = 2048;   // 4*H

// ---------------- device scratch (static, allowed) ----------------
__device__ float g_P[(size_t)B_ * T_ * A_];          // enc_proj  (98.3 MB)
__device__ float g_emb[(size_t)B_ * LQ * E_];        // gathered embeddings
__device__ float g_embg[(size_t)B_ * LQ * G4H];      // emb-part of gates + bias
__device__ float g_zc[(size_t)B_ * LQ * (H_ + A_)];  // [dec_z | c] per (b,t)
__device__ float g_WencT[A_ * A_];                   // W_enc transposed [a][d]
__device__ float g_Wrec[(size_t)G4H * 1024];         // [W_ih(:,512:1024) | W_hh] per row j
__device__ float g_bias[G4H];                        // b_ih + b_hh
__device__ float g_decz[B_ * H_];
__device__ float g_decc[B_ * H_];
__device__ float g_cvec[B_ * A_];
__device__ float g_q[B_ * A_];
__device__ float g_gpart[8 * B_ * G4H];              // split-K partials of recurrent gates
__device__ float g_e[B_ * T_];

// ---------------- f32x2 helpers (sm_100+ packed fp32 FMA) ----------------
DEV_INLINE unsigned long long pack2(float x, float y) {
    unsigned long long r;
    asm("mov.b64 %0, {%1, %2};" : "=l"(r) : "f"(x), "f"(y));
    return r;
}
DEV_INLINE void ffma2(unsigned long long& acc, unsigned long long a2, unsigned long long b2) {
    asm("fma.rn.f32x2 %0, %1, %2, %0;" : "+l"(acc) : "l"(a2), "l"(b2));
}
DEV_INLINE float lo32(unsigned long long v) { return __uint_as_float((unsigned)(v & 0xffffffffull)); }
DEV_INLINE float hi32(unsigned long long v) { return __uint_as_float((unsigned)(v >> 32)); }

DEV_INLINE float tanh_mufu(float x) {
    float y;
    asm("tanh.approx.f32 %0, %1;" : "=f"(y) : "f"(x));
    return y;
}
DEV_INLINE float sig_acc(float x) {            // accurate sigmoid for the recurrence
    return 1.f / (1.f + expf(-x));
}

// ---------------- setup kernels ----------------
__global__ void init_state_kernel() {
    int i = blockIdx.x * blockDim.x + threadIdx.x;
    if (i < B_ * H_) { g_decz[i] = 0.f; g_decc[i] = 0.f; g_cvec[i] = 0.f; }
}

__global__ void transpose_wenc_kernel(const float* __restrict__ W) {
    int idx = blockIdx.x * 256 + threadIdx.x;
    if (idx < 512 * 512) {
        int d = idx >> 9, a = idx & 511;
        g_WencT[a * 512 + d] = W[idx];
    }
}

__global__ void pack_wrec_kernel(const float* __restrict__ W_ih, const float* __restrict__ W_hh,
                                 const float* __restrict__ b_ih, const float* __restrict__ b_hh) {
    int idx = blockIdx.x * 256 + threadIdx.x;
    if (idx < G4H * 1024) {
        int j = idx >> 10, k = idx & 1023;
        g_Wrec[idx] = (k < 512) ? W_ih[(size_t)j * 1024 + 512 + k]
                                : W_hh[(size_t)j * 512 + (k - 512)];
    }
    if (idx < G4H) g_bias[idx] = b_ih[idx] + b_hh[idx];
}

__global__ void gather_emb_kernel(const int* __restrict__ ys, const float* __restrict__ emb) {
    int m = blockIdx.x;                 // m = b*101 + t
    int b = m / LQ, t = m % LQ;
    int idx = (t == 0) ? 1 : ys[b * 100 + t - 1];   // BOS=1
    const float* src = &emb[(size_t)idx * 512];
    float* dst = &g_emb[(size_t)m * 512];
    for (int k = threadIdx.x; k < 512; k += 128) dst[k] = src[k];
}

// ---------------- tuned NT SGEMM: C[M,N] = A[M,K] * B[N,K]^T (+bias) ----------------
// 128x128 tile, BK=16, 256 threads, 8x8 micro-tile, f32x2 packed FMA.
// Register-prefetched global loads + double-buffered smem, one barrier per k-tile.
// K must be a multiple of 16.
__global__ void __launch_bounds__(256) sgemm_nt(
    const float* __restrict__ A, int lda,
    const float* __restrict__ Bm, int ldb,
    const float* __restrict__ bias,
    float* __restrict__ C, int ldc,
    int M, int N, int K)
{
    __shared__ float As[2][16][132];
    __shared__ float Bs[2][16][132];

    const int tid = threadIdx.x;
    const int row0 = blockIdx.y * 128, col0 = blockIdx.x * 128;
    const int lr = tid >> 1;              // 0..127
    const int lc = (tid & 1) * 8;         // 0 or 8
    const int ty = tid >> 4, tx = tid & 15;

    const bool a_ok = (row0 + lr) < M;
    const bool b_ok = (col0 + lr) < N;
    const float* a_base = A + (size_t)(row0 + lr) * lda + lc;
    const float* b_base = Bm + (size_t)(col0 + lr) * ldb + lc;

    float ar[8], br[8];

    unsigned long long acc[8][4];
#pragma unroll
    for (int i = 0; i < 8; i++)
#pragma unroll
        for (int j = 0; j < 4; j++) acc[i][j] = 0ull;

#define LOAD_TILE(k0)                                                          \
    do {                                                                       \
        if (a_ok) {                                                            \
            float4 t0 = *(const float4*)(a_base + (k0));                       \
            float4 t1 = *(const float4*)(a_base + (k0) + 4);                   \
            ar[0]=t0.x; ar[1]=t0.y; ar[2]=t0.z; ar[3]=t0.w;                    \
            ar[4]=t1.x; ar[5]=t1.y; ar[6]=t1.z; ar[7]=t1.w;                    \
        } else { _Pragma("unroll") for (int q=0;q<8;q++) ar[q]=0.f; }          \
        if (b_ok) {                                                            \
            float4 t0 = *(const float4*)(b_base + (k0));                       \
            float4 t1 = *(const float4*)(b_base + (k0) + 4);                   \
            br[0]=t0.x; br[1]=t0.y; br[2]=t0.z; br[3]=t0.w;                    \
            br[4]=t1.x; br[5]=t1.y; br[6]=t1.z; br[7]=t1.w;                    \
        } else { _Pragma("unroll") for (int q=0;q<8;q++) br[q]=0.f; }          \
    } while (0)

#define STORE_TILE(buf)                                                        \
    do {                                                                       \
        _Pragma("unroll")                                                      \
        for (int q = 0; q < 8; q++) {                                          \
            As[buf][lc + q][lr] = ar[q];                                       \
            Bs[buf][lc + q][lr] = br[q];                                       \
        }                                                                      \
    } while (0)

    const int ntiles = K >> 4;
    LOAD_TILE(0);
    STORE_TILE(0);
    if (ntiles > 1) LOAD_TILE(16);
    __syncthreads();

    for (int kt = 0; kt < ntiles; kt++) {
        const int cur = kt & 1;
#pragma unroll
        for (int kk = 0; kk < 16; kk++) {
            float afr[8], bfr[8];
            *(float4*)&afr[0] = *(const float4*)&As[cur][kk][ty * 8];
            *(float4*)&afr[4] = *(const float4*)&As[cur][kk][ty * 8 + 4];
            *(float4*)&bfr[0] = *(const float4*)&Bs[cur][kk][tx * 8];
            *(float4*)&bfr[4] = *(const float4*)&Bs[cur][kk][tx * 8 + 4];
            unsigned long long b2[4];
            b2[0] = pack2(bfr[0], bfr[1]); b2[1] = pack2(bfr[2], bfr[3]);
            b2[2] = pack2(bfr[4], bfr[5]); b2[3] = pack2(bfr[6], bfr[7]);
#pragma unroll
            for (int i = 0; i < 8; i++) {
                unsigned long long a2 = pack2(afr[i], afr[i]);
                ffma2(acc[i][0], a2, b2[0]);
                ffma2(acc[i][1], a2, b2[1]);
                ffma2(acc[i][2], a2, b2[2]);
                ffma2(acc[i][3], a2, b2[3]);
            }
        }
        if (kt + 1 < ntiles) {
            STORE_TILE((kt + 1) & 1);
            if (kt + 2 < ntiles) LOAD_TILE((kt + 2) * 16);
        }
        __syncthreads();
    }
#undef LOAD_TILE
#undef STORE_TILE

#pragma unroll
    for (int i = 0; i < 8; i++) {
        int r = row0 + ty * 8 + i;
        if (r >= M) continue;
        float* crow = C + (size_t)r * ldc;
#pragma unroll
        for (int j4 = 0; j4 < 4; j4++) {
            int c = col0 + tx * 8 + 2 * j4;
            float vlo = lo32(acc[i][j4]);
            float vhi = hi32(acc[i][j4]);
            if (c < N)     crow[c]     = vlo + (bias ? bias[c] : 0.f);
            if (c + 1 < N) crow[c + 1] = vhi + (bias ? bias[c + 1] : 0.f);
        }
    }
}

// ---------------- per-step recurrent gates (split-K) ----------------
__global__ void __launch_bounds__(256) gates_kernel() {
    __shared__ float xh_s[32][36];
    __shared__ float w_s[32][132];
    int tid = threadIdx.x;
    int j0 = blockIdx.x * 128;
    int kz = blockIdx.y;        // 0..7, 128 K each
    int bq = tid & 7;           // b-group (4 b each)
    int jq = tid >> 3;          // j-group 0..31 (4 j each)

    unsigned long long acc[4][2];
#pragma unroll
    for (int i = 0; i < 4; i++) { acc[i][0] = 0ull; acc[i][1] = 0ull; }

    for (int kt0 = 0; kt0 < 128; kt0 += 32) {
        int kb = kz * 128 + kt0;
#pragma unroll
        for (int r = 0; r < 4; r++) {
            int lin = tid + r * 256;
            int kt = lin & 31, b = lin >> 5;
            int kk = kb + kt;
            xh_s[kt][b] = (kk < 512) ? g_cvec[b * 512 + kk] : g_decz[b * 512 + kk - 512];
        }
        {
            int jj = tid >> 1, kof = (tid & 1) * 16;
            const float* wp = &g_Wrec[(size_t)(j0 + jj) * 1024 + kb + kof];
#pragma unroll
            for (int q = 0; q < 4; q++) {
                float4 v = *(const float4*)(wp + q * 4);
                w_s[kof + q * 4 + 0][jj] = v.x; w_s[kof + q * 4 + 1][jj] = v.y;
                w_s[kof + q * 4 + 2][jj] = v.z; w_s[kof + q * 4 + 3][jj] = v.w;
            }
        }
        __syncthreads();
#pragma unroll
        for (int kt = 0; kt < 32; kt++) {
            float4 av = *(const float4*)&xh_s[kt][bq * 4];
            float4 wv = *(const float4*)&w_s[kt][jq * 4];
            unsigned long long w2a = pack2(wv.x, wv.y);
            unsigned long long w2b = pack2(wv.z, wv.w);
            unsigned long long a2;
            a2 = pack2(av.x, av.x); ffma2(acc[0][0], a2, w2a); ffma2(acc[0][1], a2, w2b);
            a2 = pack2(av.y, av.y); ffma2(acc[1][0], a2, w2a); ffma2(acc[1][1], a2, w2b);
            a2 = pack2(av.z, av.z); ffma2(acc[2][0], a2, w2a); ffma2(acc[2][1], a2, w2b);
            a2 = pack2(av.w, av.w); ffma2(acc[3][0], a2, w2a); ffma2(acc[3][1], a2, w2b);
        }
        __syncthreads();
    }
#pragma unroll
    for (int ib = 0; ib < 4; ib++) {
        int b = bq * 4 + ib;
        float* gp = &g_gpart[(size_t)kz * (B_ * G4H) + (size_t)b * G4H + j0 + jq * 4];
        gp[0] = lo32(acc[ib][0]); gp[1] = hi32(acc[ib][0]);
        gp[2] = lo32(acc[ib][1]); gp[3] = hi32(acc[ib][1]);
    }
}

// ---------------- per-step LSTM pointwise + q = dec_z @ W_dec ----------------
__global__ void __launch_bounds__(512) lstm_pw_q_kernel(const float* __restrict__ W_dec, int step) {
    __shared__ float z_s[4][512];
    int tid = threadIdx.x, bx = blockIdx.x;
#pragma unroll
    for (int sub = 0; sub < 4; sub++) {
        int b = bx * 4 + sub;
        size_t m = (size_t)b * LQ + step;
        const float* eg = &g_embg[m * G4H];
        float gi = eg[tid], gf = eg[512 + tid], gg = eg[1024 + tid], go = eg[1536 + tid];
#pragma unroll
        for (int kz = 0; kz < 8; kz++) {
            const float* gp = &g_gpart[(size_t)kz * (B_ * G4H) + (size_t)b * G4H];
            gi += gp[tid]; gf += gp[512 + tid]; gg += gp[1024 + tid]; go += gp[1536 + tid];
        }
        float cp = g_decc[b * 512 + tid];
        float cn = sig_acc(gf) * cp + sig_acc(gi) * tanhf(gg);
        float z  = sig_acc(go) * tanhf(cn);
        g_decc[b * 512 + tid] = cn;
        g_decz[b * 512 + tid] = z;
        g_zc[m * 1024 + tid] = z;
        z_s[sub][tid] = z;
    }
    __syncthreads();
    float q0 = 0.f, q1 = 0.f, q2 = 0.f, q3 = 0.f;
#pragma unroll 8
    for (int k = 0; k < 512; k++) {
        float wv = W_dec[(size_t)k * 512 + tid];
        q0 += z_s[0][k] * wv; q1 += z_s[1][k] * wv;
        q2 += z_s[2][k] * wv; q3 += z_s[3][k] * wv;
    }
    g_q[(bx * 4 + 0) * 512 + tid] = q0;
    g_q[(bx * 4 + 1) * 512 + tid] = q1;
    g_q[(bx * 4 + 2) * 512 + tid] = q2;
    g_q[(bx * 4 + 3) * 512 + tid] = q3;
}

// ---------------- per-step attention scores (MUFU.TANH) ----------------
__global__ void __launch_bounds__(256) attn_e_kernel(const int* __restrict__ enc_len,
                                                     const float* __restrict__ v_att) {
    int b = blockIdx.y;
    int len = enc_len[b];
    int t0 = blockIdx.x * 64;
    if (t0 >= len) return;
    __shared__ float q_s[512], v_s[512];
    for (int i = threadIdx.x; i < 512; i += 256) { q_s[i] = g_q[b * 512 + i]; v_s[i] = v_att[i]; }
    __syncthreads();
    int warp = threadIdx.x >> 5, lane = threadIdx.x & 31;
    for (int r = 0; r < 8; r++) {
        int t = t0 + warp * 8 + r;
        if (t >= len) break;
        const float* Pr = &g_P[((size_t)(b * T_ + t)) * 512];
        float s = 0.f;
#pragma unroll
        for (int i = 0; i < 16; i++) {
            int a = i * 32 + lane;
            s += v_s[a] * tanh_mufu(Pr[a] + q_s[a]);
        }
#pragma unroll
        for (int off = 16; off; off >>= 1) s += __shfl_xor_sync(0xffffffffu, s, off);
        if (lane == 0) g_e[b * T_ + t] = s;
    }
}

// ---------------- per-step fused softmax + ws store + context ----------------
// grid (2, B), 256 threads: each CTA handles 256 a-columns of the context;
// both CTAs redundantly compute the softmax normalizer (L2-resident e row).
__global__ void __launch_bounds__(256) softmax_context_kernel(
        const float* __restrict__ enc_pad, const int* __restrict__ enc_len,
        float* __restrict__ out_ws, int step) {
    int b = blockIdx.y, tid = threadIdx.x;
    int a = blockIdx.x * 256 + tid;
    int len = enc_len[b];
    const float* eb = &g_e[b * T_];
    __shared__ float sred[256];

    float mx = -3.4e38f;
    for (int t = tid; t < len; t += 256) mx = fmaxf(mx, eb[t]);
    sred[tid] = mx; __syncthreads();
    for (int off = 128; off; off >>= 1) {
        if (tid < off) sred[tid] = fmaxf(sred[tid], sred[tid + off]);
        __syncthreads();
    }
    mx = sred[0]; __syncthreads();
    float s = 0.f;
    for (int t = tid; t < len; t += 256) s += __expf(eb[t] - mx);
    sred[tid] = s; __syncthreads();
    for (int off = 128; off; off >>= 1) {
        if (tid < off) sred[tid] += sred[tid + off];
        __syncthreads();
    }
    float inv = 1.f / sred[0];
    __syncthreads();

    float* wsrow = (out_ws && blockIdx.x == 0) ? &out_ws[((size_t)b * LQ + step) * T_] : nullptr;
    __shared__ float w_s[256];
    float acc = 0.f;
    for (int t0 = 0; t0 < T_; t0 += 256) {
        int t = t0 + tid;
        float w = (t < len) ? __expf(eb[t] - mx) * inv : 0.f;
        w_s[tid] = w;
        if (wsrow && t < T_) wsrow[t] = w;
        __syncthreads();
        int nt = min(256, len - t0);
        if (nt > 0) {
            const float* ep = enc_pad + ((size_t)(b * T_ + t0)) * 512 + a;
            int tt = 0;
            for (; tt + 4 <= nt; tt += 4) {
                acc += w_s[tt + 0] * ep[(size_t)(tt + 0) * 512];
                acc += w_s[tt + 1] * ep[(size_t)(tt + 1) * 512];
                acc += w_s[tt + 2] * ep[(size_t)(tt + 2) * 512];
                acc += w_s[tt + 3] * ep[(size_t)(tt + 3) * 512];
            }
            for (; tt < nt; tt++) acc += w_s[tt] * ep[(size_t)tt * 512];
        }
        __syncthreads();
    }
    g_cvec[b * 512 + a] = acc;
    g_zc[((size_t)(b * LQ + step)) * 1024 + 512 + a] = acc;
}

// ---------------- final epilogue: log_softmax gather + argmax ----------------
__global__ void __launch_bounds__(256) epilogue_kernel(const int* __restrict__ ys,
                                                       const float* __restrict__ logits,
                                                       float* __restrict__ out_ylp,
                                                       float* __restrict__ out_pred) {
    int m = blockIdx.x, tid = threadIdx.x;
    const float* row = logits + (size_t)m * V_;
    __shared__ float sv[256];
    __shared__ int si[256];
    float mx = -3.4e38f; int mi = 0;
    for (int v = tid; v < V_; v += 256) {
        float x = row[v];
        if (x > mx) { mx = x; mi = v; }
    }
    sv[tid] = mx; si[tid] = mi; __syncthreads();
    for (int off = 128; off; off >>= 1) {
        if (tid < off) {
            float xo = sv[tid + off]; int io = si[tid + off];
            if (xo > sv[tid] || (xo == sv[tid] && io < si[tid])) { sv[tid] = xo; si[tid] = io; }
        }
        __syncthreads();
    }
    mx = sv[0]; int argi = si[0]; __syncthreads();
    float s = 0.f;
    for (int v = tid; v < V_; v += 256) s += __expf(row[v] - mx);
    sv[tid] = s; __syncthreads();
    for (int off = 128; off; off >>= 1) {
        if (tid < off) sv[tid] += sv[tid + off];
        __syncthreads();
    }
    if (tid == 0) {
        int b = m / LQ, t = m % LQ;
        int yo = (t < 100) ? ys[b * 100 + t] : 2;   // EOS=2
        out_ylp[m]  = row[yo] - mx - logf(sv[0]);
        out_pred[m] = (float)argi;
    }
}

// ---------------- host launch ----------------
extern "C" void kernel_launch(void* const* d_in, const int* in_sizes, int n_in,
                              void* d_out, int out_size) {
    const float* enc_pad  = (const float*)d_in[0];
    const int*   enc_len  = (const int*)  d_in[1];
    const int*   ys       = (const int*)  d_in[2];
    const float* emb_tab  = (const float*)d_in[3];
    const float* W_ih     = (const float*)d_in[4];
    const float* W_hh     = (const float*)d_in[5];
    const float* b_ih     = (const float*)d_in[6];
    const float* b_hh     = (const float*)d_in[7];
    const float* W_enc    = (const float*)d_in[8];
    const float* W_dec    = (const float*)d_in[9];
    const float* v_att    = (const float*)d_in[10];
    const float* W_out    = (const float*)d_in[11];
    const float* b_out    = (const float*)d_in[12];
    (void)in_sizes; (void)n_in;

    float* out = (float*)d_out;
    const size_t n_logits = (size_t)B_ * LQ * V_;          // 32,320,000
    const size_t n_row    = (size_t)B_ * LQ;               // 3232
    const size_t n_full   = n_logits + 2 * n_row + (size_t)B_ * LQ * T_;
    bool full = ((size_t)out_size >= n_full);

    float* out_logits = out;
    float* out_ylp  = full ? out + n_logits            : nullptr;
    float* out_pred = full ? out + n_logits + n_row    : nullptr;
    float* out_ws   = full ? out + n_logits + 2*n_row  : nullptr;

    // device scratch addresses
    float *pP, *pEmb, *pEmbG, *pZC, *pWencT, *pBias;
    cudaGetSymbolAddress((void**)&pP,     g_P);
    cudaGetSymbolAddress((void**)&pEmb,   g_emb);
    cudaGetSymbolAddress((void**)&pEmbG,  g_embg);
    cudaGetSymbolAddress((void**)&pZC,    g_zc);
    cudaGetSymbolAddress((void**)&pWencT, g_WencT);
    cudaGetSymbolAddress((void**)&pBias,  g_bias);

    // setup
    init_state_kernel<<<(B_ * H_ + 255) / 256, 256>>>();
    transpose_wenc_kernel<<<(512 * 512 + 255) / 256, 256>>>(W_enc);
    pack_wrec_kernel<<<(G4H * 1024 + 255) / 256, 256>>>(W_ih, W_hh, b_ih, b_hh);
    gather_emb_kernel<<<B_ * LQ, 128>>>(ys, emb_tab);

    // enc_proj = enc_pad @ W_enc  (NT form via W_enc^T)
    {
        dim3 g((A_ + 127) / 128, (B_ * T_ + 127) / 128);
        sgemm_nt<<<g, 256>>>(enc_pad, A_, pWencT, A_, nullptr, pP, A_, B_ * T_, A_, A_);
    }
    // emb-part of gates (+combined bias)
    {
        dim3 g((G4H + 127) / 128, (B_ * LQ + 127) / 128);
        sgemm_nt<<<g, 256>>>(pEmb, E_, W_ih, E_ + A_, pBias, pEmbG, G4H, B_ * LQ, G4H, E_);
    }

    // sequential decode loop
    for (int t = 0; t < LQ; t++) {
        gates_kernel<<<dim3(16, 8), 256>>>();
        lstm_pw_q_kernel<<<8, 512>>>(W_dec, t);
        attn_e_kernel<<<dim3((T_ + 63) / 64, B_), 256>>>(enc_len, v_att);
        softmax_context_kernel<<<dim3(2, B_), 256>>>(enc_pad, enc_len, out_ws, t);
    }

    // logits = [dec_z | c] @ W_out^T + b_out  -> directly into d_out
    {
        dim3 g((V_ + 127) / 128, (B_ * LQ + 127) / 128);
        sgemm_nt<<<g, 256>>>(pZC, H_ + A_, W_out, H_ + A_, b_out, out_logits, V_,
                             B_ * LQ, V_, H_ + A_);
    }
    if (full) {
        epilogue_kernel<<<B_ * LQ, 256>>>(ys, out_logits, out_ylp, out_pred);
    }
}

// round 3
// speedup vs baseline: 3.2543x; 3.1837x over previous
#include <cuda_runtime.h>
#include <cstdint>
#include <cstddef>

#define DEV_INLINE __device__ __forceinline__

constexpr int B_  = 32;
constexpr int T_  = 1500;
constexpr int A_  = 512;
constexpr int E_  = 512;
constexpr int H_  = 512;
constexpr int V_  = 10000;
constexpr int LQ  = 101;    // L+1
constexpr int G4H = 2048;   // 4*H
constexpr int NEC = 12;     // attn_e T-chunks (12*128 >= 1500)
constexpr int NCC = 6;      // context T-chunks (6*250 = 1500)

// ---------------- device scratch (static, allowed) ----------------
__device__ float g_P[(size_t)B_ * T_ * A_];          // enc_proj  (98.3 MB)
__device__ float g_emb[(size_t)B_ * LQ * E_];        // gathered embeddings
__device__ float g_embg[(size_t)B_ * LQ * G4H];      // emb-part of gates + bias
__device__ float g_zc[(size_t)B_ * LQ * (H_ + A_)];  // [dec_z | c] per (b,t)
__device__ float g_WencT[A_ * A_];                   // W_enc transposed [a][d]
__device__ float g_Wrec[(size_t)G4H * 1024];         // [W_ih(:,512:1024) | W_hh] per row j
__device__ float g_bias[G4H];                        // b_ih + b_hh
__device__ float g_decz[B_ * H_];
__device__ float g_decc[B_ * H_];
__device__ float g_cvec[B_ * A_];
__device__ float g_q[B_ * A_];
__device__ float g_gpart[8 * B_ * G4H];              // split-K partials of recurrent gates
__device__ float g_ue[B_ * T_];                      // exp(e) masked
__device__ float g_epart[B_ * NEC];                  // per-chunk sums of ue
__device__ float g_cpart[(size_t)NCC * B_ * A_];     // context partials

// ---------------- f32x2 helpers (sm_100+ packed fp32 FMA) ----------------
DEV_INLINE unsigned long long pack2(float x, float y) {
    unsigned long long r;
    asm("mov.b64 %0, {%1, %2};" : "=l"(r) : "f"(x), "f"(y));
    return r;
}
DEV_INLINE void ffma2(unsigned long long& acc, unsigned long long a2, unsigned long long b2) {
    asm("fma.rn.f32x2 %0, %1, %2, %0;" : "+l"(acc) : "l"(a2), "l"(b2));
}
DEV_INLINE float lo32(unsigned long long v) { return __uint_as_float((unsigned)(v & 0xffffffffull)); }
DEV_INLINE float hi32(unsigned long long v) { return __uint_as_float((unsigned)(v >> 32)); }

DEV_INLINE float tanh_mufu(float x) {
    float y;
    asm("tanh.approx.f32 %0, %1;" : "=f"(y) : "f"(x));
    return y;
}
DEV_INLINE float sig_acc(float x) { return 1.f / (1.f + expf(-x)); }

// ---------------- setup kernels ----------------
__global__ void init_state_kernel() {
    int i = blockIdx.x * blockDim.x + threadIdx.x;
    if (i < B_ * H_) { g_decz[i] = 0.f; g_decc[i] = 0.f; g_cvec[i] = 0.f; }
}

__global__ void transpose_wenc_kernel(const float* __restrict__ W) {
    int idx = blockIdx.x * 256 + threadIdx.x;
    if (idx < 512 * 512) {
        int d = idx >> 9, a = idx & 511;
        g_WencT[a * 512 + d] = W[idx];
    }
}

__global__ void pack_wrec_kernel(const float* __restrict__ W_ih, const float* __restrict__ W_hh,
                                 const float* __restrict__ b_ih, const float* __restrict__ b_hh) {
    int idx = blockIdx.x * 256 + threadIdx.x;
    if (idx < G4H * 1024) {
        int j = idx >> 10, k = idx & 1023;
        g_Wrec[idx] = (k < 512) ? W_ih[(size_t)j * 1024 + 512 + k]
                                : W_hh[(size_t)j * 512 + (k - 512)];
    }
    if (idx < G4H) g_bias[idx] = b_ih[idx] + b_hh[idx];
}

__global__ void gather_emb_kernel(const int* __restrict__ ys, const float* __restrict__ emb) {
    int m = blockIdx.x;                 // m = b*101 + t
    int b = m / LQ, t = m % LQ;
    int idx = (t == 0) ? 1 : ys[b * 100 + t - 1];   // BOS=1
    const float* src = &emb[(size_t)idx * 512];
    float* dst = &g_emb[(size_t)m * 512];
    for (int k = threadIdx.x; k < 512; k += 128) dst[k] = src[k];
}

// ---------------- tuned NT SGEMM (unchanged from R2) ----------------
__global__ void __launch_bounds__(256) sgemm_nt(
    const float* __restrict__ A, int lda,
    const float* __restrict__ Bm, int ldb,
    const float* __restrict__ bias,
    float* __restrict__ C, int ldc,
    int M, int N, int K)
{
    __shared__ float As[2][16][132];
    __shared__ float Bs[2][16][132];

    const int tid = threadIdx.x;
    const int row0 = blockIdx.y * 128, col0 = blockIdx.x * 128;
    const int lr = tid >> 1;
    const int lc = (tid & 1) * 8;
    const int ty = tid >> 4, tx = tid & 15;

    const bool a_ok = (row0 + lr) < M;
    const bool b_ok = (col0 + lr) < N;
    const float* a_base = A + (size_t)(row0 + lr) * lda + lc;
    const float* b_base = Bm + (size_t)(col0 + lr) * ldb + lc;

    float ar[8], br[8];
    unsigned long long acc[8][4];
#pragma unroll
    for (int i = 0; i < 8; i++)
#pragma unroll
        for (int j = 0; j < 4; j++) acc[i][j] = 0ull;

#define LOAD_TILE(k0)                                                          \
    do {                                                                       \
        if (a_ok) {                                                            \
            float4 t0 = *(const float4*)(a_base + (k0));                       \
            float4 t1 = *(const float4*)(a_base + (k0) + 4);                   \
            ar[0]=t0.x; ar[1]=t0.y; ar[2]=t0.z; ar[3]=t0.w;                    \
            ar[4]=t1.x; ar[5]=t1.y; ar[6]=t1.z; ar[7]=t1.w;                    \
        } else { _Pragma("unroll") for (int q=0;q<8;q++) ar[q]=0.f; }          \
        if (b_ok) {                                                            \
            float4 t0 = *(const float4*)(b_base + (k0));                       \
            float4 t1 = *(const float4*)(b_base + (k0) + 4);                   \
            br[0]=t0.x; br[1]=t0.y; br[2]=t0.z; br[3]=t0.w;                    \
            br[4]=t1.x; br[5]=t1.y; br[6]=t1.z; br[7]=t1.w;                    \
        } else { _Pragma("unroll") for (int q=0;q<8;q++) br[q]=0.f; }          \
    } while (0)

#define STORE_TILE(buf)                                                        \
    do {                                                                       \
        _Pragma("unroll")                                                      \
        for (int q = 0; q < 8; q++) {                                          \
            As[buf][lc + q][lr] = ar[q];                                       \
            Bs[buf][lc + q][lr] = br[q];                                       \
        }                                                                      \
    } while (0)

    const int ntiles = K >> 4;
    LOAD_TILE(0);
    STORE_TILE(0);
    if (ntiles > 1) LOAD_TILE(16);
    __syncthreads();

    for (int kt = 0; kt < ntiles; kt++) {
        const int cur = kt & 1;
#pragma unroll
        for (int kk = 0; kk < 16; kk++) {
            float afr[8], bfr[8];
            *(float4*)&afr[0] = *(const float4*)&As[cur][kk][ty * 8];
            *(float4*)&afr[4] = *(const float4*)&As[cur][kk][ty * 8 + 4];
            *(float4*)&bfr[0] = *(const float4*)&Bs[cur][kk][tx * 8];
            *(float4*)&bfr[4] = *(const float4*)&Bs[cur][kk][tx * 8 + 4];
            unsigned long long b2[4];
            b2[0] = pack2(bfr[0], bfr[1]); b2[1] = pack2(bfr[2], bfr[3]);
            b2[2] = pack2(bfr[4], bfr[5]); b2[3] = pack2(bfr[6], bfr[7]);
#pragma unroll
            for (int i = 0; i < 8; i++) {
                unsigned long long a2 = pack2(afr[i], afr[i]);
                ffma2(acc[i][0], a2, b2[0]);
                ffma2(acc[i][1], a2, b2[1]);
                ffma2(acc[i][2], a2, b2[2]);
                ffma2(acc[i][3], a2, b2[3]);
            }
        }
        if (kt + 1 < ntiles) {
            STORE_TILE((kt + 1) & 1);
            if (kt + 2 < ntiles) LOAD_TILE((kt + 2) * 16);
        }
        __syncthreads();
    }
#undef LOAD_TILE
#undef STORE_TILE

#pragma unroll
    for (int i = 0; i < 8; i++) {
        int r = row0 + ty * 8 + i;
        if (r >= M) continue;
        float* crow = C + (size_t)r * ldc;
#pragma unroll
        for (int j4 = 0; j4 < 4; j4++) {
            int c = col0 + tx * 8 + 2 * j4;
            float vlo = lo32(acc[i][j4]);
            float vhi = hi32(acc[i][j4]);
            if (c < N)     crow[c]     = vlo + (bias ? bias[c] : 0.f);
            if (c + 1 < N) crow[c + 1] = vhi + (bias ? bias[c + 1] : 0.f);
        }
    }
}

// ---------------- per-step recurrent gates (split-K) ----------------
__global__ void __launch_bounds__(256) gates_kernel() {
    __shared__ float xh_s[32][36];
    __shared__ float w_s[32][132];
    int tid = threadIdx.x;
    int j0 = blockIdx.x * 128;
    int kz = blockIdx.y;        // 0..7, 128 K each
    int bq = tid & 7;
    int jq = tid >> 3;

    unsigned long long acc[4][2];
#pragma unroll
    for (int i = 0; i < 4; i++) { acc[i][0] = 0ull; acc[i][1] = 0ull; }

    for (int kt0 = 0; kt0 < 128; kt0 += 32) {
        int kb = kz * 128 + kt0;
#pragma unroll
        for (int r = 0; r < 4; r++) {
            int lin = tid + r * 256;
            int kt = lin & 31, b = lin >> 5;
            int kk = kb + kt;
            xh_s[kt][b] = (kk < 512) ? g_cvec[b * 512 + kk] : g_decz[b * 512 + kk - 512];
        }
        {
            int jj = tid >> 1, kof = (tid & 1) * 16;
            const float* wp = &g_Wrec[(size_t)(j0 + jj) * 1024 + kb + kof];
#pragma unroll
            for (int q = 0; q < 4; q++) {
                float4 v = *(const float4*)(wp + q * 4);
                w_s[kof + q * 4 + 0][jj] = v.x; w_s[kof + q * 4 + 1][jj] = v.y;
                w_s[kof + q * 4 + 2][jj] = v.z; w_s[kof + q * 4 + 3][jj] = v.w;
            }
        }
        __syncthreads();
#pragma unroll
        for (int kt = 0; kt < 32; kt++) {
            float4 av = *(const float4*)&xh_s[kt][bq * 4];
            float4 wv = *(const float4*)&w_s[kt][jq * 4];
            unsigned long long w2a = pack2(wv.x, wv.y);
            unsigned long long w2b = pack2(wv.z, wv.w);
            unsigned long long a2;
            a2 = pack2(av.x, av.x); ffma2(acc[0][0], a2, w2a); ffma2(acc[0][1], a2, w2b);
            a2 = pack2(av.y, av.y); ffma2(acc[1][0], a2, w2a); ffma2(acc[1][1], a2, w2b);
            a2 = pack2(av.z, av.z); ffma2(acc[2][0], a2, w2a); ffma2(acc[2][1], a2, w2b);
            a2 = pack2(av.w, av.w); ffma2(acc[3][0], a2, w2a); ffma2(acc[3][1], a2, w2b);
        }
        __syncthreads();
    }
#pragma unroll
    for (int ib = 0; ib < 4; ib++) {
        int b = bq * 4 + ib;
        float* gp = &g_gpart[(size_t)kz * (B_ * G4H) + (size_t)b * G4H + j0 + jq * 4];
        gp[0] = lo32(acc[ib][0]); gp[1] = hi32(acc[ib][0]);
        gp[2] = lo32(acc[ib][1]); gp[3] = hi32(acc[ib][1]);
    }
}

// ---------------- per-step LSTM pointwise + split-K q GEMV ----------------
// grid 32 (one b per CTA), 1024 threads.
__global__ void __launch_bounds__(1024) lstm_pw_q_kernel(const float* __restrict__ W_dec, int step) {
    int b = blockIdx.x;
    int tid = threadIdx.x;
    __shared__ float z_s[512];
    __shared__ float qp[1024];

    if (tid < 512) {
        size_t m = (size_t)b * LQ + step;
        const float* eg = &g_embg[m * G4H];
        float gi = eg[tid], gf = eg[512 + tid], gg = eg[1024 + tid], go = eg[1536 + tid];
#pragma unroll
        for (int kz = 0; kz < 8; kz++) {
            const float* gp = &g_gpart[(size_t)kz * (B_ * G4H) + (size_t)b * G4H];
            gi += gp[tid]; gf += gp[512 + tid]; gg += gp[1024 + tid]; go += gp[1536 + tid];
        }
        float cp = g_decc[b * 512 + tid];
        float cn = sig_acc(gf) * cp + sig_acc(gi) * tanhf(gg);
        float z  = sig_acc(go) * tanhf(cn);
        g_decc[b * 512 + tid] = cn;
        g_decz[b * 512 + tid] = z;
        g_zc[m * 1024 + tid] = z;
        z_s[tid] = z;
    }
    __syncthreads();

    int j = tid & 511;
    int k0 = (tid >> 9) * 256;   // 0 or 256
    float q = 0.f;
    const float* wd = W_dec + (size_t)k0 * 512 + j;
#pragma unroll 8
    for (int k = 0; k < 256; k++) {
        q += z_s[k0 + k] * wd[(size_t)k * 512];
    }
    qp[tid] = q;
    __syncthreads();
    if (tid < 512) g_q[b * 512 + tid] = qp[tid] + qp[tid + 512];
}

// ---------------- per-step attention scores -> ue = exp(e), partial sums ----
// No max-pass: |e| <= ||v_att||_1 (~8.2), exp cannot overflow.
// grid (NEC=12, B), 256 threads. Chunk of 128 t per CTA, 16 per warp, 2 at a time.
__global__ void __launch_bounds__(256) attn_e_kernel(const int* __restrict__ enc_len,
                                                     const float* __restrict__ v_att) {
    int b = blockIdx.y;
    int len = enc_len[b];
    int tid = threadIdx.x, warp = tid >> 5, lane = tid & 31;
    __shared__ float q_s[512], v_s[512];
    __shared__ float wred[8];
    for (int i = tid; i < 512; i += 256) { q_s[i] = g_q[b * 512 + i]; v_s[i] = v_att[i]; }
    __syncthreads();

    int tbase = blockIdx.x * 128 + warp * 16;
    float wsum = 0.f;
#pragma unroll 1
    for (int r = 0; r < 16; r += 2) {
        int t0 = tbase + r;
        if (t0 >= T_) break;
        int t1 = t0 + 1;
        bool m0 = (t0 < len);
        bool m1 = (t1 < len) && (t1 < T_);
        float s0 = 0.f, s1 = 0.f;
        const float* P0 = &g_P[((size_t)b * T_ + t0) * 512];
        if (m0 || m1) {
#pragma unroll
            for (int i = 0; i < 16; i++) {
                int a = i * 32 + lane;
                float p0 = m0 ? __ldcs(P0 + a) : 0.f;
                float p1 = m1 ? __ldcs(P0 + 512 + a) : 0.f;
                s0 += v_s[a] * tanh_mufu(p0 + q_s[a]);
                s1 += v_s[a] * tanh_mufu(p1 + q_s[a]);
            }
#pragma unroll
            for (int off = 16; off; off >>= 1) {
                s0 += __shfl_xor_sync(0xffffffffu, s0, off);
                s1 += __shfl_xor_sync(0xffffffffu, s1, off);
            }
        }
        if (lane == 0) {
            float u0 = m0 ? __expf(s0) : 0.f;
            float u1 = m1 ? __expf(s1) : 0.f;
            g_ue[b * T_ + t0] = u0;
            if (t1 < T_) g_ue[b * T_ + t1] = u1;
            wsum += u0 + u1;
        }
    }
    if (lane == 0) wred[warp] = wsum;
    __syncthreads();
    if (tid == 0) {
        float s = 0.f;
#pragma unroll
        for (int i = 0; i < 8; i++) s += wred[i];
        g_epart[b * NEC + blockIdx.x] = s;
    }
}

// ---------------- per-step context (split-T) + ws store ----------------
// grid (NCC=6, B), 256 threads. Each CTA: 250 t-rows, all 512 a-cols (2/thread).
__global__ void __launch_bounds__(256) context_kernel(
        const float* __restrict__ enc_pad, const int* __restrict__ enc_len,
        float* __restrict__ out_ws, int step) {
    int b = blockIdx.y, tc = blockIdx.x, tid = threadIdx.x;
    int len = enc_len[b];

    __shared__ float s_inv;
    __shared__ float w_s[256];
    if (tid == 0) {
        float s = 0.f;
#pragma unroll
        for (int i = 0; i < NEC; i++) s += g_epart[b * NEC + i];
        s_inv = 1.f / s;
    }
    __syncthreads();
    float inv = s_inv;

    int t0 = tc * 250;
    int t1 = min(t0 + 250, T_);
    // compute w for this chunk, write ws, stage in smem
    {
        int t = t0 + tid;
        float w = 0.f;
        if (t < t1) {
            w = (t < len) ? g_ue[b * T_ + t] * inv : 0.f;
            if (out_ws) out_ws[((size_t)b * LQ + step) * T_ + t] = w;
        }
        if (tid < 250) w_s[tid] = w;
    }
    __syncthreads();

    int nt = min(t1, len) - t0;
    if (nt < 0) nt = 0;
    float acc0 = 0.f, acc1 = 0.f;
    const float* ep = enc_pad + ((size_t)b * T_ + t0) * 512;
    int a0 = tid, a1 = tid + 256;
    int ttm = nt & ~7;
    for (int tt = 0; tt < ttm; tt += 8) {
#pragma unroll
        for (int u = 0; u < 8; u++) {
            float w = w_s[tt + u];
            acc0 += w * __ldcs(ep + (size_t)(tt + u) * 512 + a0);
            acc1 += w * __ldcs(ep + (size_t)(tt + u) * 512 + a1);
        }
    }
    for (int tt = ttm; tt < nt; tt++) {
        float w = w_s[tt];
        acc0 += w * __ldcs(ep + (size_t)tt * 512 + a0);
        acc1 += w * __ldcs(ep + (size_t)tt * 512 + a1);
    }
    float* cp = &g_cpart[((size_t)tc * B_ + b) * A_];
    cp[a0] = acc0;
    cp[a1] = acc1;
}

// ---------------- per-step context reduce ----------------
__global__ void __launch_bounds__(512) reduce_c_kernel(int step) {
    int b = blockIdx.x, a = threadIdx.x;
    float s = 0.f;
#pragma unroll
    for (int tc = 0; tc < NCC; tc++) s += g_cpart[((size_t)tc * B_ + b) * A_ + a];
    g_cvec[b * 512 + a] = s;
    g_zc[((size_t)b * LQ + step) * 1024 + 512 + a] = s;
}

// ---------------- final epilogue: log_softmax gather + argmax ----------------
__global__ void __launch_bounds__(256) epilogue_kernel(const int* __restrict__ ys,
                                                       const float* __restrict__ logits,
                                                       float* __restrict__ out_ylp,
                                                       float* __restrict__ out_pred) {
    int m = blockIdx.x, tid = threadIdx.x;
    const float* row = logits + (size_t)m * V_;
    __shared__ float sv[256];
    __shared__ int si[256];
    float mx = -3.4e38f; int mi = 0;
    for (int v = tid; v < V_; v += 256) {
        float x = row[v];
        if (x > mx) { mx = x; mi = v; }
    }
    sv[tid] = mx; si[tid] = mi; __syncthreads();
    for (int off = 128; off; off >>= 1) {
        if (tid < off) {
            float xo = sv[tid + off]; int io = si[tid + off];
            if (xo > sv[tid] || (xo == sv[tid] && io < si[tid])) { sv[tid] = xo; si[tid] = io; }
        }
        __syncthreads();
    }
    mx = sv[0]; int argi = si[0]; __syncthreads();
    float s = 0.f;
    for (int v = tid; v < V_; v += 256) s += __expf(row[v] - mx);
    sv[tid] = s; __syncthreads();
    for (int off = 128; off; off >>= 1) {
        if (tid < off) sv[tid] += sv[tid + off];
        __syncthreads();
    }
    if (tid == 0) {
        int b = m / LQ, t = m % LQ;
        int yo = (t < 100) ? ys[b * 100 + t] : 2;   // EOS=2
        out_ylp[m]  = row[yo] - mx - logf(sv[0]);
        out_pred[m] = (float)argi;
    }
}

// ---------------- host launch ----------------
extern "C" void kernel_launch(void* const* d_in, const int* in_sizes, int n_in,
                              void* d_out, int out_size) {
    const float* enc_pad  = (const float*)d_in[0];
    const int*   enc_len  = (const int*)  d_in[1];
    const int*   ys       = (const int*)  d_in[2];
    const float* emb_tab  = (const float*)d_in[3];
    const float* W_ih     = (const float*)d_in[4];
    const float* W_hh     = (const float*)d_in[5];
    const float* b_ih     = (const float*)d_in[6];
    const float* b_hh     = (const float*)d_in[7];
    const float* W_enc    = (const float*)d_in[8];
    const float* W_dec    = (const float*)d_in[9];
    const float* v_att    = (const float*)d_in[10];
    const float* W_out    = (const float*)d_in[11];
    const float* b_out    = (const float*)d_in[12];
    (void)in_sizes; (void)n_in;

    float* out = (float*)d_out;
    const size_t n_logits = (size_t)B_ * LQ * V_;
    const size_t n_row    = (size_t)B_ * LQ;
    const size_t n_full   = n_logits + 2 * n_row + (size_t)B_ * LQ * T_;
    bool full = ((size_t)out_size >= n_full);

    float* out_logits = out;
    float* out_ylp  = full ? out + n_logits            : nullptr;
    float* out_pred = full ? out + n_logits + n_row    : nullptr;
    float* out_ws   = full ? out + n_logits + 2*n_row  : nullptr;

    float *pP, *pEmb, *pEmbG, *pZC, *pWencT, *pBias;
    cudaGetSymbolAddress((void**)&pP,     g_P);
    cudaGetSymbolAddress((void**)&pEmb,   g_emb);
    cudaGetSymbolAddress((void**)&pEmbG,  g_embg);
    cudaGetSymbolAddress((void**)&pZC,    g_zc);
    cudaGetSymbolAddress((void**)&pWencT, g_WencT);
    cudaGetSymbolAddress((void**)&pBias,  g_bias);

    // setup
    init_state_kernel<<<(B_ * H_ + 255) / 256, 256>>>();
    transpose_wenc_kernel<<<(512 * 512 + 255) / 256, 256>>>(W_enc);
    pack_wrec_kernel<<<(G4H * 1024 + 255) / 256, 256>>>(W_ih, W_hh, b_ih, b_hh);
    gather_emb_kernel<<<B_ * LQ, 128>>>(ys, emb_tab);

    // enc_proj = enc_pad @ W_enc
    {
        dim3 g((A_ + 127) / 128, (B_ * T_ + 127) / 128);
        sgemm_nt<<<g, 256>>>(enc_pad, A_, pWencT, A_, nullptr, pP, A_, B_ * T_, A_, A_);
    }
    // emb-part of gates (+combined bias)
    {
        dim3 g((G4H + 127) / 128, (B_ * LQ + 127) / 128);
        sgemm_nt<<<g, 256>>>(pEmb, E_, W_ih, E_ + A_, pBias, pEmbG, G4H, B_ * LQ, G4H, E_);
    }

    // sequential decode loop
    for (int t = 0; t < LQ; t++) {
        gates_kernel<<<dim3(16, 8), 256>>>();
        lstm_pw_q_kernel<<<B_, 1024>>>(W_dec, t);
        attn_e_kernel<<<dim3(NEC, B_), 256>>>(enc_len, v_att);
        context_kernel<<<dim3(NCC, B_), 256>>>(enc_pad, enc_len, out_ws, t);
        reduce_c_kernel<<<B_, 512>>>(t);
    }

    // logits = [dec_z | c] @ W_out^T + b_out
    {
        dim3 g((V_ + 127) / 128, (B_ * LQ + 127) / 128);
        sgemm_nt<<<g, 256>>>(pZC, H_ + A_, W_out, H_ + A_, b_out, out_logits, V_,
                             B_ * LQ, V_, H_ + A_);
    }
    if (full) {
        epilogue_kernel<<<B_ * LQ, 256>>>(ys, out_logits, out_ylp, out_pred);
    }
}

// round 4
// speedup vs baseline: 4.0369x; 1.2405x over previous
#include <cuda_runtime.h>
#include <cuda_fp16.h>
#include <cstdint>
#include <cstddef>

#define DEV_INLINE __device__ __forceinline__

constexpr int B_  = 32;
constexpr int T_  = 1500;
constexpr int A_  = 512;
constexpr int E_  = 512;
constexpr int H_  = 512;
constexpr int V_  = 10000;
constexpr int LQ  = 101;    // L+1
constexpr int G4H = 2048;   // 4*H
constexpr int NEC = 12;     // attn_e T-chunks (12*128 >= 1500)
constexpr int NCC = 6;      // context T-chunks (6*250 = 1500)

// ---------------- device scratch (static, allowed) ----------------
__device__ __half g_Ph[(size_t)B_ * T_ * A_];        // enc_proj in fp16 (49 MB)
__device__ __half g_encH[(size_t)B_ * T_ * A_];      // enc_pad in fp16 (49 MB)
__device__ float g_emb[(size_t)B_ * LQ * E_];        // gathered embeddings
__device__ float g_embg[(size_t)B_ * LQ * G4H];      // emb-part of gates + bias
__device__ float g_zc[(size_t)B_ * LQ * (H_ + A_)];  // [dec_z | c] per (b,t)
__device__ float g_WencT[A_ * A_];                   // W_enc transposed [a][d]
__device__ float g_Wrec[(size_t)G4H * 1024];         // [W_ih(:,512:1024) | W_hh]
__device__ float g_bias[G4H];                        // b_ih + b_hh
__device__ float g_decz[B_ * H_];
__device__ float g_decc[B_ * H_];
__device__ float g_q[B_ * A_];
__device__ float g_gpart[8 * B_ * G4H];              // split-K partials of recurrent gates
__device__ float g_ue[B_ * T_];                      // exp(e) masked
__device__ float g_epart[B_ * NEC];                  // per-chunk sums of ue
__device__ float g_cpart[(size_t)NCC * B_ * A_];     // context partials

// ---------------- f32x2 helpers ----------------
DEV_INLINE unsigned long long pack2(float x, float y) {
    unsigned long long r;
    asm("mov.b64 %0, {%1, %2};" : "=l"(r) : "f"(x), "f"(y));
    return r;
}
DEV_INLINE void ffma2(unsigned long long& acc, unsigned long long a2, unsigned long long b2) {
    asm("fma.rn.f32x2 %0, %1, %2, %0;" : "+l"(acc) : "l"(a2), "l"(b2));
}
DEV_INLINE float lo32(unsigned long long v) { return __uint_as_float((unsigned)(v & 0xffffffffull)); }
DEV_INLINE float hi32(unsigned long long v) { return __uint_as_float((unsigned)(v >> 32)); }

DEV_INLINE float tanh_mufu(float x) {
    float y;
    asm("tanh.approx.f32 %0, %1;" : "=f"(y) : "f"(x));
    return y;
}
DEV_INLINE float sig_acc(float x) { return 1.f / (1.f + expf(-x)); }

// ---------------- setup kernels ----------------
__global__ void init_state_kernel() {
    int i = blockIdx.x * blockDim.x + threadIdx.x;
    if (i < B_ * H_) { g_decz[i] = 0.f; g_decc[i] = 0.f; }
    if (i < NCC * B_ * A_) g_cpart[i] = 0.f;
}

__global__ void convert_enc_kernel(const float* __restrict__ enc) {
    size_t i = (size_t)blockIdx.x * blockDim.x + threadIdx.x;   // half2 index
    size_t n2 = (size_t)B_ * T_ * A_ / 2;
    if (i < n2) {
        float2 f = ((const float2*)enc)[i];
        ((__half2*)g_encH)[i] = __floats2half2_rn(f.x, f.y);
    }
}

__global__ void transpose_wenc_kernel(const float* __restrict__ W) {
    int idx = blockIdx.x * 256 + threadIdx.x;
    if (idx < 512 * 512) {
        int d = idx >> 9, a = idx & 511;
        g_WencT[a * 512 + d] = W[idx];
    }
}

__global__ void pack_wrec_kernel(const float* __restrict__ W_ih, const float* __restrict__ W_hh,
                                 const float* __restrict__ b_ih, const float* __restrict__ b_hh) {
    int idx = blockIdx.x * 256 + threadIdx.x;
    if (idx < G4H * 1024) {
        int j = idx >> 10, k = idx & 1023;
        g_Wrec[idx] = (k < 512) ? W_ih[(size_t)j * 1024 + 512 + k]
                                : W_hh[(size_t)j * 512 + (k - 512)];
    }
    if (idx < G4H) g_bias[idx] = b_ih[idx] + b_hh[idx];
}

__global__ void gather_emb_kernel(const int* __restrict__ ys, const float* __restrict__ emb) {
    int m = blockIdx.x;                 // m = b*101 + t
    int b = m / LQ, t = m % LQ;
    int idx = (t == 0) ? 1 : ys[b * 100 + t - 1];   // BOS=1
    const float* src = &emb[(size_t)idx * 512];
    float* dst = &g_emb[(size_t)m * 512];
    for (int k = threadIdx.x; k < 512; k += 128) dst[k] = src[k];
}

// ---------------- tuned NT SGEMM (templated output type) ----------------
DEV_INLINE void store_out(float* p, float v) { *p = v; }
DEV_INLINE void store_out(__half* p, float v) { *p = __float2half_rn(v); }

template <typename OutT>
__global__ void __launch_bounds__(256) sgemm_nt(
    const float* __restrict__ A, int lda,
    const float* __restrict__ Bm, int ldb,
    const float* __restrict__ bias,
    OutT* __restrict__ C, int ldc,
    int M, int N, int K)
{
    __shared__ float As[2][16][132];
    __shared__ float Bs[2][16][132];

    const int tid = threadIdx.x;
    const int row0 = blockIdx.y * 128, col0 = blockIdx.x * 128;
    const int lr = tid >> 1;
    const int lc = (tid & 1) * 8;
    const int ty = tid >> 4, tx = tid & 15;

    const bool a_ok = (row0 + lr) < M;
    const bool b_ok = (col0 + lr) < N;
    const float* a_base = A + (size_t)(row0 + lr) * lda + lc;
    const float* b_base = Bm + (size_t)(col0 + lr) * ldb + lc;

    float ar[8], br[8];
    unsigned long long acc[8][4];
#pragma unroll
    for (int i = 0; i < 8; i++)
#pragma unroll
        for (int j = 0; j < 4; j++) acc[i][j] = 0ull;

#define LOAD_TILE(k0)                                                          \
    do {                                                                       \
        if (a_ok) {                                                            \
            float4 t0 = *(const float4*)(a_base + (k0));                       \
            float4 t1 = *(const float4*)(a_base + (k0) + 4);                   \
            ar[0]=t0.x; ar[1]=t0.y; ar[2]=t0.z; ar[3]=t0.w;                    \
            ar[4]=t1.x; ar[5]=t1.y; ar[6]=t1.z; ar[7]=t1.w;                    \
        } else { _Pragma("unroll") for (int q=0;q<8;q++) ar[q]=0.f; }          \
        if (b_ok) {                                                            \
            float4 t0 = *(const float4*)(b_base + (k0));                       \
            float4 t1 = *(const float4*)(b_base + (k0) + 4);                   \
            br[0]=t0.x; br[1]=t0.y; br[2]=t0.z; br[3]=t0.w;                    \
            br[4]=t1.x; br[5]=t1.y; br[6]=t1.z; br[7]=t1.w;                    \
        } else { _Pragma("unroll") for (int q=0;q<8;q++) br[q]=0.f; }          \
    } while (0)

#define STORE_TILE(buf)                                                        \
    do {                                                                       \
        _Pragma("unroll")                                                      \
        for (int q = 0; q < 8; q++) {                                          \
            As[buf][lc + q][lr] = ar[q];                                       \
            Bs[buf][lc + q][lr] = br[q];                                       \
        }                                                                      \
    } while (0)

    const int ntiles = K >> 4;
    LOAD_TILE(0);
    STORE_TILE(0);
    if (ntiles > 1) LOAD_TILE(16);
    __syncthreads();

    for (int kt = 0; kt < ntiles; kt++) {
        const int cur = kt & 1;
#pragma unroll
        for (int kk = 0; kk < 16; kk++) {
            float afr[8], bfr[8];
            *(float4*)&afr[0] = *(const float4*)&As[cur][kk][ty * 8];
            *(float4*)&afr[4] = *(const float4*)&As[cur][kk][ty * 8 + 4];
            *(float4*)&bfr[0] = *(const float4*)&Bs[cur][kk][tx * 8];
            *(float4*)&bfr[4] = *(const float4*)&Bs[cur][kk][tx * 8 + 4];
            unsigned long long b2[4];
            b2[0] = pack2(bfr[0], bfr[1]); b2[1] = pack2(bfr[2], bfr[3]);
            b2[2] = pack2(bfr[4], bfr[5]); b2[3] = pack2(bfr[6], bfr[7]);
#pragma unroll
            for (int i = 0; i < 8; i++) {
                unsigned long long a2 = pack2(afr[i], afr[i]);
                ffma2(acc[i][0], a2, b2[0]);
                ffma2(acc[i][1], a2, b2[1]);
                ffma2(acc[i][2], a2, b2[2]);
                ffma2(acc[i][3], a2, b2[3]);
            }
        }
        if (kt + 1 < ntiles) {
            STORE_TILE((kt + 1) & 1);
            if (kt + 2 < ntiles) LOAD_TILE((kt + 2) * 16);
        }
        __syncthreads();
    }
#undef LOAD_TILE
#undef STORE_TILE

#pragma unroll
    for (int i = 0; i < 8; i++) {
        int r = row0 + ty * 8 + i;
        if (r >= M) continue;
        OutT* crow = C + (size_t)r * ldc;
#pragma unroll
        for (int j4 = 0; j4 < 4; j4++) {
            int c = col0 + tx * 8 + 2 * j4;
            float vlo = lo32(acc[i][j4]);
            float vhi = hi32(acc[i][j4]);
            if (c < N)     store_out(crow + c,     vlo + (bias ? bias[c] : 0.f));
            if (c + 1 < N) store_out(crow + c + 1, vhi + (bias ? bias[c + 1] : 0.f));
        }
    }
}

// ---------------- per-step recurrent gates (split-K) ----------------
// Reads c_prev as sum of NCC context partials (fused reduce); j0==0 blocks
// also write the zc c-part for step-1.
__global__ void __launch_bounds__(256) gates_kernel(int step) {
    __shared__ float xh_s[32][36];
    __shared__ float w_s[32][132];
    int tid = threadIdx.x;
    int j0 = blockIdx.x * 128;
    int kz = blockIdx.y;        // 0..7, 128 K each
    int bq = tid & 7;
    int jq = tid >> 3;

    unsigned long long acc[4][2];
#pragma unroll
    for (int i = 0; i < 4; i++) { acc[i][0] = 0ull; acc[i][1] = 0ull; }

    for (int kt0 = 0; kt0 < 128; kt0 += 32) {
        int kb = kz * 128 + kt0;
#pragma unroll
        for (int r = 0; r < 4; r++) {
            int lin = tid + r * 256;
            int kt = lin & 31, b = lin >> 5;
            int kk = kb + kt;
            float v;
            if (kk < 512) {
                v = 0.f;
#pragma unroll
                for (int tc = 0; tc < NCC; tc++)
                    v += g_cpart[((size_t)tc * B_ + b) * A_ + kk];
                if (blockIdx.x == 0 && step > 0)
                    g_zc[((size_t)b * LQ + step - 1) * 1024 + 512 + kk] = v;
            } else {
                v = g_decz[b * 512 + kk - 512];
            }
            xh_s[kt][b] = v;
        }
        {
            int jj = tid >> 1, kof = (tid & 1) * 16;
            const float* wp = &g_Wrec[(size_t)(j0 + jj) * 1024 + kb + kof];
#pragma unroll
            for (int q = 0; q < 4; q++) {
                float4 v = *(const float4*)(wp + q * 4);
                w_s[kof + q * 4 + 0][jj] = v.x; w_s[kof + q * 4 + 1][jj] = v.y;
                w_s[kof + q * 4 + 2][jj] = v.z; w_s[kof + q * 4 + 3][jj] = v.w;
            }
        }
        __syncthreads();
#pragma unroll
        for (int kt = 0; kt < 32; kt++) {
            float4 av = *(const float4*)&xh_s[kt][bq * 4];
            float4 wv = *(const float4*)&w_s[kt][jq * 4];
            unsigned long long w2a = pack2(wv.x, wv.y);
            unsigned long long w2b = pack2(wv.z, wv.w);
            unsigned long long a2;
            a2 = pack2(av.x, av.x); ffma2(acc[0][0], a2, w2a); ffma2(acc[0][1], a2, w2b);
            a2 = pack2(av.y, av.y); ffma2(acc[1][0], a2, w2a); ffma2(acc[1][1], a2, w2b);
            a2 = pack2(av.z, av.z); ffma2(acc[2][0], a2, w2a); ffma2(acc[2][1], a2, w2b);
            a2 = pack2(av.w, av.w); ffma2(acc[3][0], a2, w2a); ffma2(acc[3][1], a2, w2b);
        }
        __syncthreads();
    }
#pragma unroll
    for (int ib = 0; ib < 4; ib++) {
        int b = bq * 4 + ib;
        float* gp = &g_gpart[(size_t)kz * (B_ * G4H) + (size_t)b * G4H + j0 + jq * 4];
        gp[0] = lo32(acc[ib][0]); gp[1] = hi32(acc[ib][0]);
        gp[2] = lo32(acc[ib][1]); gp[3] = hi32(acc[ib][1]);
    }
}

// ---------------- per-step LSTM pointwise + split-K q GEMV ----------------
__global__ void __launch_bounds__(1024) lstm_pw_q_kernel(const float* __restrict__ W_dec, int step) {
    int b = blockIdx.x;
    int tid = threadIdx.x;
    __shared__ float z_s[512];
    __shared__ float qp[1024];

    if (tid < 512) {
        size_t m = (size_t)b * LQ + step;
        const float* eg = &g_embg[m * G4H];
        float gi = eg[tid], gf = eg[512 + tid], gg = eg[1024 + tid], go = eg[1536 + tid];
#pragma unroll
        for (int kz = 0; kz < 8; kz++) {
            const float* gp = &g_gpart[(size_t)kz * (B_ * G4H) + (size_t)b * G4H];
            gi += gp[tid]; gf += gp[512 + tid]; gg += gp[1024 + tid]; go += gp[1536 + tid];
        }
        float cp = g_decc[b * 512 + tid];
        float cn = sig_acc(gf) * cp + sig_acc(gi) * tanhf(gg);
        float z  = sig_acc(go) * tanhf(cn);
        g_decc[b * 512 + tid] = cn;
        g_decz[b * 512 + tid] = z;
        g_zc[m * 1024 + tid] = z;
        z_s[tid] = z;
    }
    __syncthreads();

    int j = tid & 511;
    int k0 = (tid >> 9) * 256;   // 0 or 256
    float q = 0.f;
    const float* wd = W_dec + (size_t)k0 * 512 + j;
#pragma unroll 8
    for (int k = 0; k < 256; k++) {
        q += z_s[k0 + k] * wd[(size_t)k * 512];
    }
    qp[tid] = q;
    __syncthreads();
    if (tid < 512) g_q[b * 512 + tid] = qp[tid] + qp[tid + 512];
}

// ---------------- per-step attention scores (fp16 P, reg-resident v/q) ----
// grid (NEC=12, B), 256 threads; warp handles 16 t-rows, 2 at a time.
// Lane owns 16 a-indices: [lane*8 .. lane*8+7] and [256+lane*8 .. +7].
__global__ void __launch_bounds__(256) attn_e_kernel(const int* __restrict__ enc_len,
                                                     const float* __restrict__ v_att) {
    int b = blockIdx.y;
    int len = enc_len[b];
    int tid = threadIdx.x, warp = tid >> 5, lane = tid & 31;
    __shared__ float wred[8];

    float qv[16], vv[16];
    {
        const float* qb = &g_q[b * 512 + lane * 8];
        *(float4*)&qv[0]  = *(const float4*)(qb);
        *(float4*)&qv[4]  = *(const float4*)(qb + 4);
        *(float4*)&qv[8]  = *(const float4*)(qb + 256);
        *(float4*)&qv[12] = *(const float4*)(qb + 260);
        const float* vb = &v_att[lane * 8];
        *(float4*)&vv[0]  = *(const float4*)(vb);
        *(float4*)&vv[4]  = *(const float4*)(vb + 4);
        *(float4*)&vv[8]  = *(const float4*)(vb + 256);
        *(float4*)&vv[12] = *(const float4*)(vb + 260);
    }

    int tbase = blockIdx.x * 128 + warp * 16;
    float wsum = 0.f;
#pragma unroll 1
    for (int r = 0; r < 16; r += 2) {
        int t0 = tbase + r;
        if (t0 >= T_) break;
        int t1 = t0 + 1;
        bool m0 = (t0 < len);
        bool m1 = (t1 < len) && (t1 < T_);
        float s0 = 0.f, s1 = 0.f;
        if (m0 || m1) {
            const __half* P0 = &g_Ph[((size_t)b * T_ + t0) * 512];
            uint4 u0a, u0b, u1a, u1b;
            u0a = m0 ? *(const uint4*)(P0 + lane * 8)        : make_uint4(0,0,0,0);
            u0b = m0 ? *(const uint4*)(P0 + 256 + lane * 8)  : make_uint4(0,0,0,0);
            u1a = m1 ? *(const uint4*)(P0 + 512 + lane * 8)       : make_uint4(0,0,0,0);
            u1b = m1 ? *(const uint4*)(P0 + 768 + lane * 8)       : make_uint4(0,0,0,0);
            const __half2* h0a = (const __half2*)&u0a;
            const __half2* h0b = (const __half2*)&u0b;
            const __half2* h1a = (const __half2*)&u1a;
            const __half2* h1b = (const __half2*)&u1b;
#pragma unroll
            for (int j = 0; j < 4; j++) {
                float2 f0 = __half22float2(h0a[j]);
                float2 f1 = __half22float2(h1a[j]);
                s0 += vv[2*j]   * tanh_mufu(f0.x + qv[2*j]);
                s0 += vv[2*j+1] * tanh_mufu(f0.y + qv[2*j+1]);
                s1 += vv[2*j]   * tanh_mufu(f1.x + qv[2*j]);
                s1 += vv[2*j+1] * tanh_mufu(f1.y + qv[2*j+1]);
            }
#pragma unroll
            for (int j = 0; j < 4; j++) {
                float2 f0 = __half22float2(h0b[j]);
                float2 f1 = __half22float2(h1b[j]);
                s0 += vv[8+2*j]   * tanh_mufu(f0.x + qv[8+2*j]);
                s0 += vv[8+2*j+1] * tanh_mufu(f0.y + qv[8+2*j+1]);
                s1 += vv[8+2*j]   * tanh_mufu(f1.x + qv[8+2*j]);
                s1 += vv[8+2*j+1] * tanh_mufu(f1.y + qv[8+2*j+1]);
            }
#pragma unroll
            for (int off = 16; off; off >>= 1) {
                s0 += __shfl_xor_sync(0xffffffffu, s0, off);
                s1 += __shfl_xor_sync(0xffffffffu, s1, off);
            }
        }
        if (lane == 0) {
            float u0 = m0 ? __expf(s0) : 0.f;
            float u1 = m1 ? __expf(s1) : 0.f;
            g_ue[b * T_ + t0] = u0;
            if (t1 < T_) g_ue[b * T_ + t1] = u1;
            wsum += u0 + u1;
        }
    }
    if (lane == 0) wred[warp] = wsum;
    __syncthreads();
    if (tid == 0) {
        float s = 0.f;
#pragma unroll
        for (int i = 0; i < 8; i++) s += wred[i];
        g_epart[b * NEC + blockIdx.x] = s;
    }
}

// ---------------- per-step context (split-T, fp16 enc) + ws store ----------
// grid (NCC=6, B), 256 threads; thread handles half2 column pair a = 2*tid.
__global__ void __launch_bounds__(256) context_kernel(
        const int* __restrict__ enc_len,
        float* __restrict__ out_ws, int step) {
    int b = blockIdx.y, tc = blockIdx.x, tid = threadIdx.x;
    int len = enc_len[b];

    __shared__ float s_inv;
    __shared__ float w_s[256];
    if (tid == 0) {
        float s = 0.f;
#pragma unroll
        for (int i = 0; i < NEC; i++) s += g_epart[b * NEC + i];
        s_inv = 1.f / s;
    }
    __syncthreads();
    float inv = s_inv;

    int t0 = tc * 250;
    int t1 = min(t0 + 250, T_);
    {
        int t = t0 + tid;
        float w = 0.f;
        if (t < t1) {
            w = (t < len) ? g_ue[b * T_ + t] * inv : 0.f;
            if (out_ws) out_ws[((size_t)b * LQ + step) * T_ + t] = w;
        }
        if (tid < 250) w_s[tid] = w;
    }
    __syncthreads();

    int nt = min(t1, len) - t0;
    if (nt < 0) nt = 0;
    float acc0 = 0.f, acc1 = 0.f;
    const __half2* ep2 = (const __half2*)(&g_encH[((size_t)b * T_ + t0) * 512]) + tid;
    int ttm = nt & ~7;
    for (int tt = 0; tt < ttm; tt += 8) {
#pragma unroll
        for (int u = 0; u < 8; u++) {
            float w = w_s[tt + u];
            float2 f = __half22float2(__ldcs((const __half2*)(ep2 + (size_t)(tt + u) * 256)));
            acc0 += w * f.x;
            acc1 += w * f.y;
        }
    }
    for (int tt = ttm; tt < nt; tt++) {
        float w = w_s[tt];
        float2 f = __half22float2(__ldcs((const __half2*)(ep2 + (size_t)tt * 256)));
        acc0 += w * f.x;
        acc1 += w * f.y;
    }
    float* cp = &g_cpart[((size_t)tc * B_ + b) * A_];
    cp[2 * tid]     = acc0;
    cp[2 * tid + 1] = acc1;
}

// ---------------- final context reduce (step 100 only) ----------------
__global__ void __launch_bounds__(512) final_c_kernel(int step) {
    int b = blockIdx.x, a = threadIdx.x;
    float s = 0.f;
#pragma unroll
    for (int tc = 0; tc < NCC; tc++) s += g_cpart[((size_t)tc * B_ + b) * A_ + a];
    g_zc[((size_t)b * LQ + step) * 1024 + 512 + a] = s;
}

// ---------------- final epilogue: log_softmax gather + argmax ----------------
__global__ void __launch_bounds__(256) epilogue_kernel(const int* __restrict__ ys,
                                                       const float* __restrict__ logits,
                                                       float* __restrict__ out_ylp,
                                                       float* __restrict__ out_pred) {
    int m = blockIdx.x, tid = threadIdx.x;
    const float* row = logits + (size_t)m * V_;
    __shared__ float sv[256];
    __shared__ int si[256];
    float mx = -3.4e38f; int mi = 0;
    for (int v = tid; v < V_; v += 256) {
        float x = row[v];
        if (x > mx) { mx = x; mi = v; }
    }
    sv[tid] = mx; si[tid] = mi; __syncthreads();
    for (int off = 128; off; off >>= 1) {
        if (tid < off) {
            float xo = sv[tid + off]; int io = si[tid + off];
            if (xo > sv[tid] || (xo == sv[tid] && io < si[tid])) { sv[tid] = xo; si[tid] = io; }
        }
        __syncthreads();
    }
    mx = sv[0]; int argi = si[0]; __syncthreads();
    float s = 0.f;
    for (int v = tid; v < V_; v += 256) s += __expf(row[v] - mx);
    sv[tid] = s; __syncthreads();
    for (int off = 128; off; off >>= 1) {
        if (tid < off) sv[tid] += sv[tid + off];
        __syncthreads();
    }
    if (tid == 0) {
        int b = m / LQ, t = m % LQ;
        int yo = (t < 100) ? ys[b * 100 + t] : 2;   // EOS=2
        out_ylp[m]  = row[yo] - mx - logf(sv[0]);
        out_pred[m] = (float)argi;
    }
}

// ---------------- host launch ----------------
extern "C" void kernel_launch(void* const* d_in, const int* in_sizes, int n_in,
                              void* d_out, int out_size) {
    const float* enc_pad  = (const float*)d_in[0];
    const int*   enc_len  = (const int*)  d_in[1];
    const int*   ys       = (const int*)  d_in[2];
    const float* emb_tab  = (const float*)d_in[3];
    const float* W_ih     = (const float*)d_in[4];
    const float* W_hh     = (const float*)d_in[5];
    const float* b_ih     = (const float*)d_in[6];
    const float* b_hh     = (const float*)d_in[7];
    const float* W_enc    = (const float*)d_in[8];
    const float* W_dec    = (const float*)d_in[9];
    const float* v_att    = (const float*)d_in[10];
    const float* W_out    = (const float*)d_in[11];
    const float* b_out    = (const float*)d_in[12];
    (void)in_sizes; (void)n_in;

    float* out = (float*)d_out;
    const size_t n_logits = (size_t)B_ * LQ * V_;
    const size_t n_row    = (size_t)B_ * LQ;
    const size_t n_full   = n_logits + 2 * n_row + (size_t)B_ * LQ * T_;
    bool full = ((size_t)out_size >= n_full);

    float* out_logits = out;
    float* out_ylp  = full ? out + n_logits            : nullptr;
    float* out_pred = full ? out + n_logits + n_row    : nullptr;
    float* out_ws   = full ? out + n_logits + 2*n_row  : nullptr;

    float *pEmb, *pEmbG, *pZC, *pWencT, *pBias;
    __half* pPh;
    cudaGetSymbolAddress((void**)&pPh,    g_Ph);
    cudaGetSymbolAddress((void**)&pEmb,   g_emb);
    cudaGetSymbolAddress((void**)&pEmbG,  g_embg);
    cudaGetSymbolAddress((void**)&pZC,    g_zc);
    cudaGetSymbolAddress((void**)&pWencT, g_WencT);
    cudaGetSymbolAddress((void**)&pBias,  g_bias);

    // setup
    init_state_kernel<<<(NCC * B_ * A_ + 255) / 256, 256>>>();
    convert_enc_kernel<<<(B_ * T_ * A_ / 2 + 255) / 256, 256>>>(enc_pad);
    transpose_wenc_kernel<<<(512 * 512 + 255) / 256, 256>>>(W_enc);
    pack_wrec_kernel<<<(G4H * 1024 + 255) / 256, 256>>>(W_ih, W_hh, b_ih, b_hh);
    gather_emb_kernel<<<B_ * LQ, 128>>>(ys, emb_tab);

    // enc_proj = enc_pad @ W_enc  -> fp16
    {
        dim3 g((A_ + 127) / 128, (B_ * T_ + 127) / 128);
        sgemm_nt<__half><<<g, 256>>>(enc_pad, A_, pWencT, A_, nullptr, pPh, A_,
                                     B_ * T_, A_, A_);
    }
    // emb-part of gates (+combined bias)
    {
        dim3 g((G4H + 127) / 128, (B_ * LQ + 127) / 128);
        sgemm_nt<float><<<g, 256>>>(pEmb, E_, W_ih, E_ + A_, pBias, pEmbG, G4H,
                                    B_ * LQ, G4H, E_);
    }

    // sequential decode loop (4 kernels/step)
    for (int t = 0; t < LQ; t++) {
        gates_kernel<<<dim3(16, 8), 256>>>(t);
        lstm_pw_q_kernel<<<B_, 1024>>>(W_dec, t);
        attn_e_kernel<<<dim3(NEC, B_), 256>>>(enc_len, v_att);
        context_kernel<<<dim3(NCC, B_), 256>>>(enc_len, out_ws, t);
    }
    final_c_kernel<<<B_, 512>>>(LQ - 1);

    // logits = [dec_z | c] @ W_out^T + b_out
    {
        dim3 g((V_ + 127) / 128, (B_ * LQ + 127) / 128);
        sgemm_nt<float><<<g, 256>>>(pZC, H_ + A_, W_out, H_ + A_, b_out, out_logits, V_,
                                    B_ * LQ, V_, H_ + A_);
    }
    if (full) {
        epilogue_kernel<<<B_ * LQ, 256>>>(ys, out_logits, out_ylp, out_pred);
    }
}

// round 5
// speedup vs baseline: 4.0760x; 1.0097x over previous
#include <cuda_runtime.h>
#include <cuda_fp16.h>
#include <cstdint>
#include <cstddef>

#define DEV_INLINE __device__ __forceinline__

constexpr int B_  = 32;
constexpr int T_  = 1500;
constexpr int A_  = 512;
constexpr int E_  = 512;
constexpr int H_  = 512;
constexpr int V_  = 10000;
constexpr int LQ  = 101;    // L+1
constexpr int G4H = 2048;   // 4*H
constexpr int NEC = 24;     // attn_e T-chunks (24*64 >= 1500)
constexpr int NCC = 12;     // context T-chunks (12*125 = 1500)

// ---------------- device scratch (static, allowed) ----------------
__device__ __half g_Ph[(size_t)B_ * T_ * A_];        // enc_proj in fp16 (49 MB)
__device__ __half g_encH[(size_t)B_ * T_ * A_];      // enc_pad in fp16 (49 MB)
__device__ float g_emb[(size_t)B_ * LQ * E_];        // gathered embeddings
__device__ float g_embg[(size_t)B_ * LQ * G4H];      // emb-part of gates + bias
__device__ float g_zc[(size_t)B_ * LQ * (H_ + A_)];  // [dec_z | c] per (b,t)
__device__ float g_WencT[A_ * A_];                   // W_enc transposed [a][d]
__device__ float g_Wrec[(size_t)G4H * 1024];         // [W_ih(:,512:1024) | W_hh]
__device__ float g_bias[G4H];                        // b_ih + b_hh
__device__ float g_decz[B_ * H_];
__device__ float g_decc[B_ * H_];
__device__ float g_q[B_ * A_];
__device__ float g_gpart[8 * B_ * G4H];              // split-K partials of recurrent gates
__device__ float g_ue[B_ * T_];                      // exp(e) masked
__device__ float g_epart[B_ * NEC];                  // per-chunk sums of ue
__device__ float g_cpart[(size_t)NCC * B_ * A_];     // context partials

// ---------------- f32x2 helpers ----------------
DEV_INLINE void ffma2(unsigned long long& acc, unsigned long long a2, unsigned long long b2) {
    asm("fma.rn.f32x2 %0, %1, %2, %0;" : "+l"(acc) : "l"(a2), "l"(b2));
}
DEV_INLINE float lo32(unsigned long long v) { return __uint_as_float((unsigned)(v & 0xffffffffull)); }
DEV_INLINE float hi32(unsigned long long v) { return __uint_as_float((unsigned)(v >> 32)); }

DEV_INLINE float tanh_mufu(float x) {
    float y;
    asm("tanh.approx.f32 %0, %1;" : "=f"(y) : "f"(x));
    return y;
}
DEV_INLINE float sig_acc(float x) { return 1.f / (1.f + expf(-x)); }

// ---------------- setup kernels ----------------
__global__ void init_state_kernel() {
    int i = blockIdx.x * blockDim.x + threadIdx.x;
    if (i < B_ * H_) { g_decz[i] = 0.f; g_decc[i] = 0.f; }
    if (i < NCC * B_ * A_) g_cpart[i] = 0.f;
}

__global__ void convert_enc_kernel(const float* __restrict__ enc) {
    size_t i = (size_t)blockIdx.x * blockDim.x + threadIdx.x;   // half2 index
    size_t n2 = (size_t)B_ * T_ * A_ / 2;
    if (i < n2) {
        float2 f = ((const float2*)enc)[i];
        ((__half2*)g_encH)[i] = __floats2half2_rn(f.x, f.y);
    }
}

__global__ void transpose_wenc_kernel(const float* __restrict__ W) {
    int idx = blockIdx.x * 256 + threadIdx.x;
    if (idx < 512 * 512) {
        int d = idx >> 9, a = idx & 511;
        g_WencT[a * 512 + d] = W[idx];
    }
}

__global__ void pack_wrec_kernel(const float* __restrict__ W_ih, const float* __restrict__ W_hh,
                                 const float* __restrict__ b_ih, const float* __restrict__ b_hh) {
    int idx = blockIdx.x * 256 + threadIdx.x;
    if (idx < G4H * 1024) {
        int j = idx >> 10, k = idx & 1023;
        g_Wrec[idx] = (k < 512) ? W_ih[(size_t)j * 1024 + 512 + k]
                                : W_hh[(size_t)j * 512 + (k - 512)];
    }
    if (idx < G4H) g_bias[idx] = b_ih[idx] + b_hh[idx];
}

__global__ void gather_emb_kernel(const int* __restrict__ ys, const float* __restrict__ emb) {
    int m = blockIdx.x;                 // m = b*101 + t
    int b = m / LQ, t = m % LQ;
    int idx = (t == 0) ? 1 : ys[b * 100 + t - 1];   // BOS=1
    const float* src = &emb[(size_t)idx * 512];
    float* dst = &g_emb[(size_t)m * 512];
    for (int k = threadIdx.x; k < 512; k += 128) dst[k] = src[k];
}

// ---------------- tuned NT SGEMM: zero-pack inner loop ----------------
// C[M,N] = A[M,K] * B[N,K]^T (+bias). 128x128 tile, BK=16, 256 threads,
// 8x8 micro-tile. A stored DUPLICATED in smem so ulonglong2 LDS yields
// pack2(a,a) for free; B read as ulonglong2 = pack2(b0,b1) for free.
DEV_INLINE void store_out(float* p, float v) { *p = v; }
DEV_INLINE void store_out(__half* p, float v) { *p = __float2half_rn(v); }

template <typename OutT>
__global__ void __launch_bounds__(256, 2) sgemm_nt(
    const float* __restrict__ A, int lda,
    const float* __restrict__ Bm, int ldb,
    const float* __restrict__ bias,
    OutT* __restrict__ C, int ldc,
    int M, int N, int K)
{
    __shared__ float Asd[2][16][256];   // duplicated A: [kk][2r]=[kk][2r+1]=a_r
    __shared__ float Bs[2][16][128];

    const int tid = threadIdx.x;
    const int row0 = blockIdx.y * 128, col0 = blockIdx.x * 128;
    const int lr = tid >> 1;
    const int lc = (tid & 1) * 8;
    const int ty = tid >> 4, tx = tid & 15;

    const bool a_ok = (row0 + lr) < M;
    const bool b_ok = (col0 + lr) < N;
    const float* a_base = A + (size_t)(row0 + lr) * lda + lc;
    const float* b_base = Bm + (size_t)(col0 + lr) * ldb + lc;

    float ar[8], br[8];
    unsigned long long acc[8][4];
#pragma unroll
    for (int i = 0; i < 8; i++)
#pragma unroll
        for (int j = 0; j < 4; j++) acc[i][j] = 0ull;

#define LOAD_TILE(k0)                                                          \
    do {                                                                       \
        if (a_ok) {                                                            \
            float4 t0 = *(const float4*)(a_base + (k0));                       \
            float4 t1 = *(const float4*)(a_base + (k0) + 4);                   \
            ar[0]=t0.x; ar[1]=t0.y; ar[2]=t0.z; ar[3]=t0.w;                    \
            ar[4]=t1.x; ar[5]=t1.y; ar[6]=t1.z; ar[7]=t1.w;                    \
        } else { _Pragma("unroll") for (int q=0;q<8;q++) ar[q]=0.f; }          \
        if (b_ok) {                                                            \
            float4 t0 = *(const float4*)(b_base + (k0));                       \
            float4 t1 = *(const float4*)(b_base + (k0) + 4);                   \
            br[0]=t0.x; br[1]=t0.y; br[2]=t0.z; br[3]=t0.w;                    \
            br[4]=t1.x; br[5]=t1.y; br[6]=t1.z; br[7]=t1.w;                    \
        } else { _Pragma("unroll") for (int q=0;q<8;q++) br[q]=0.f; }          \
    } while (0)

#define STORE_TILE(buf)                                                        \
    do {                                                                       \
        _Pragma("unroll")                                                      \
        for (int q = 0; q < 8; q++) {                                          \
            Asd[buf][lc + q][2 * lr]     = ar[q];                              \
            Asd[buf][lc + q][2 * lr + 1] = ar[q];                              \
            Bs[buf][lc + q][lr]          = br[q];                              \
        }                                                                      \
    } while (0)

    const int ntiles = K >> 4;
    LOAD_TILE(0);
    STORE_TILE(0);
    if (ntiles > 1) LOAD_TILE(16);
    __syncthreads();

    for (int kt = 0; kt < ntiles; kt++) {
        const int cur = kt & 1;
#pragma unroll
        for (int kk = 0; kk < 16; kk++) {
            const ulonglong2* arow = (const ulonglong2*)&Asd[cur][kk][ty * 16];
            const ulonglong2* brow = (const ulonglong2*)&Bs[cur][kk][tx * 8];
            ulonglong2 a01 = arow[0];
            ulonglong2 a23 = arow[1];
            ulonglong2 a45 = arow[2];
            ulonglong2 a67 = arow[3];
            ulonglong2 bu0 = brow[0];
            ulonglong2 bu1 = brow[1];
            unsigned long long a2v[8] = {a01.x, a01.y, a23.x, a23.y,
                                         a45.x, a45.y, a67.x, a67.y};
            unsigned long long b2v[4] = {bu0.x, bu0.y, bu1.x, bu1.y};
#pragma unroll
            for (int i = 0; i < 8; i++) {
#pragma unroll
                for (int j = 0; j < 4; j++) ffma2(acc[i][j], a2v[i], b2v[j]);
            }
        }
        if (kt + 1 < ntiles) {
            STORE_TILE((kt + 1) & 1);
            if (kt + 2 < ntiles) LOAD_TILE((kt + 2) * 16);
        }
        __syncthreads();
    }
#undef LOAD_TILE
#undef STORE_TILE

#pragma unroll
    for (int i = 0; i < 8; i++) {
        int r = row0 + ty * 8 + i;
        if (r >= M) continue;
        OutT* crow = C + (size_t)r * ldc;
#pragma unroll
        for (int j4 = 0; j4 < 4; j4++) {
            int c = col0 + tx * 8 + 2 * j4;
            float vlo = lo32(acc[i][j4]);
            float vhi = hi32(acc[i][j4]);
            if (c < N)     store_out(crow + c,     vlo + (bias ? bias[c] : 0.f));
            if (c + 1 < N) store_out(crow + c + 1, vhi + (bias ? bias[c + 1] : 0.f));
        }
    }
}

DEV_INLINE unsigned long long pack2(float x, float y) {
    unsigned long long r;
    asm("mov.b64 %0, {%1, %2};" : "=l"(r) : "f"(x), "f"(y));
    return r;
}

// ---------------- per-step recurrent gates (split-K) ----------------
// Reads c_prev as sum of NCC context partials (fused reduce); j0==0 blocks
// also write the zc c-part for step-1.
__global__ void __launch_bounds__(256) gates_kernel(int step) {
    __shared__ float xh_s[32][36];
    __shared__ float w_s[32][132];
    int tid = threadIdx.x;
    int j0 = blockIdx.x * 128;
    int kz = blockIdx.y;        // 0..7, 128 K each
    int bq = tid & 7;
    int jq = tid >> 3;

    unsigned long long acc[4][2];
#pragma unroll
    for (int i = 0; i < 4; i++) { acc[i][0] = 0ull; acc[i][1] = 0ull; }

    for (int kt0 = 0; kt0 < 128; kt0 += 32) {
        int kb = kz * 128 + kt0;
#pragma unroll
        for (int r = 0; r < 4; r++) {
            int lin = tid + r * 256;
            int kt = lin & 31, b = lin >> 5;
            int kk = kb + kt;
            float v;
            if (kk < 512) {
                v = 0.f;
#pragma unroll
                for (int tc = 0; tc < NCC; tc++)
                    v += g_cpart[((size_t)tc * B_ + b) * A_ + kk];
                if (blockIdx.x == 0 && step > 0)
                    g_zc[((size_t)b * LQ + step - 1) * 1024 + 512 + kk] = v;
            } else {
                v = g_decz[b * 512 + kk - 512];
            }
            xh_s[kt][b] = v;
        }
        {
            int jj = tid >> 1, kof = (tid & 1) * 16;
            const float* wp = &g_Wrec[(size_t)(j0 + jj) * 1024 + kb + kof];
#pragma unroll
            for (int q = 0; q < 4; q++) {
                float4 v = *(const float4*)(wp + q * 4);
                w_s[kof + q * 4 + 0][jj] = v.x; w_s[kof + q * 4 + 1][jj] = v.y;
                w_s[kof + q * 4 + 2][jj] = v.z; w_s[kof + q * 4 + 3][jj] = v.w;
            }
        }
        __syncthreads();
#pragma unroll
        for (int kt = 0; kt < 32; kt++) {
            float4 av = *(const float4*)&xh_s[kt][bq * 4];
            float4 wv = *(const float4*)&w_s[kt][jq * 4];
            unsigned long long w2a = pack2(wv.x, wv.y);
            unsigned long long w2b = pack2(wv.z, wv.w);
            unsigned long long a2;
            a2 = pack2(av.x, av.x); ffma2(acc[0][0], a2, w2a); ffma2(acc[0][1], a2, w2b);
            a2 = pack2(av.y, av.y); ffma2(acc[1][0], a2, w2a); ffma2(acc[1][1], a2, w2b);
            a2 = pack2(av.z, av.z); ffma2(acc[2][0], a2, w2a); ffma2(acc[2][1], a2, w2b);
            a2 = pack2(av.w, av.w); ffma2(acc[3][0], a2, w2a); ffma2(acc[3][1], a2, w2b);
        }
        __syncthreads();
    }
#pragma unroll
    for (int ib = 0; ib < 4; ib++) {
        int b = bq * 4 + ib;
        float* gp = &g_gpart[(size_t)kz * (B_ * G4H) + (size_t)b * G4H + j0 + jq * 4];
        gp[0] = lo32(acc[ib][0]); gp[1] = hi32(acc[ib][0]);
        gp[2] = lo32(acc[ib][1]); gp[3] = hi32(acc[ib][1]);
    }
}

// ---------------- per-step LSTM pointwise + split-K q GEMV ----------------
__global__ void __launch_bounds__(1024) lstm_pw_q_kernel(const float* __restrict__ W_dec, int step) {
    int b = blockIdx.x;
    int tid = threadIdx.x;
    __shared__ float z_s[512];
    __shared__ float qp[1024];

    if (tid < 512) {
        size_t m = (size_t)b * LQ + step;
        const float* eg = &g_embg[m * G4H];
        float gi = eg[tid], gf = eg[512 + tid], gg = eg[1024 + tid], go = eg[1536 + tid];
#pragma unroll
        for (int kz = 0; kz < 8; kz++) {
            const float* gp = &g_gpart[(size_t)kz * (B_ * G4H) + (size_t)b * G4H];
            gi += gp[tid]; gf += gp[512 + tid]; gg += gp[1024 + tid]; go += gp[1536 + tid];
        }
        float cp = g_decc[b * 512 + tid];
        float cn = sig_acc(gf) * cp + sig_acc(gi) * tanhf(gg);
        float z  = sig_acc(go) * tanhf(cn);
        g_decc[b * 512 + tid] = cn;
        g_decz[b * 512 + tid] = z;
        g_zc[m * 1024 + tid] = z;
        z_s[tid] = z;
    }
    __syncthreads();

    int j = tid & 511;
    int k0 = (tid >> 9) * 256;   // 0 or 256
    float q = 0.f;
    const float* wd = W_dec + (size_t)k0 * 512 + j;
#pragma unroll 8
    for (int k = 0; k < 256; k++) {
        q += z_s[k0 + k] * wd[(size_t)k * 512];
    }
    qp[tid] = q;
    __syncthreads();
    if (tid < 512) g_q[b * 512 + tid] = qp[tid] + qp[tid + 512];
}

// ---------------- per-step attention scores (fp16 P, reg-resident v/q) ----
// grid (NEC=24, B), 256 threads; warp handles 8 t-rows, 2 at a time.
__global__ void __launch_bounds__(256) attn_e_kernel(const int* __restrict__ enc_len,
                                                     const float* __restrict__ v_att) {
    int b = blockIdx.y;
    int len = enc_len[b];
    int tid = threadIdx.x, warp = tid >> 5, lane = tid & 31;
    __shared__ float wred[8];

    float qv[16], vv[16];
    {
        const float* qb = &g_q[b * 512 + lane * 8];
        *(float4*)&qv[0]  = *(const float4*)(qb);
        *(float4*)&qv[4]  = *(const float4*)(qb + 4);
        *(float4*)&qv[8]  = *(const float4*)(qb + 256);
        *(float4*)&qv[12] = *(const float4*)(qb + 260);
        const float* vb = &v_att[lane * 8];
        *(float4*)&vv[0]  = *(const float4*)(vb);
        *(float4*)&vv[4]  = *(const float4*)(vb + 4);
        *(float4*)&vv[8]  = *(const float4*)(vb + 256);
        *(float4*)&vv[12] = *(const float4*)(vb + 260);
    }

    int tbase = blockIdx.x * 64 + warp * 8;
    float wsum = 0.f;
#pragma unroll 1
    for (int r = 0; r < 8; r += 2) {
        int t0 = tbase + r;
        if (t0 >= T_) break;
        int t1 = t0 + 1;
        bool m0 = (t0 < len);
        bool m1 = (t1 < len) && (t1 < T_);
        float s0 = 0.f, s1 = 0.f;
        if (m0 || m1) {
            const __half* P0 = &g_Ph[((size_t)b * T_ + t0) * 512];
            uint4 u0a, u0b, u1a, u1b;
            u0a = m0 ? *(const uint4*)(P0 + lane * 8)        : make_uint4(0,0,0,0);
            u0b = m0 ? *(const uint4*)(P0 + 256 + lane * 8)  : make_uint4(0,0,0,0);
            u1a = m1 ? *(const uint4*)(P0 + 512 + lane * 8)  : make_uint4(0,0,0,0);
            u1b = m1 ? *(const uint4*)(P0 + 768 + lane * 8)  : make_uint4(0,0,0,0);
            const __half2* h0a = (const __half2*)&u0a;
            const __half2* h0b = (const __half2*)&u0b;
            const __half2* h1a = (const __half2*)&u1a;
            const __half2* h1b = (const __half2*)&u1b;
#pragma unroll
            for (int j = 0; j < 4; j++) {
                float2 f0 = __half22float2(h0a[j]);
                float2 f1 = __half22float2(h1a[j]);
                s0 += vv[2*j]   * tanh_mufu(f0.x + qv[2*j]);
                s0 += vv[2*j+1] * tanh_mufu(f0.y + qv[2*j+1]);
                s1 += vv[2*j]   * tanh_mufu(f1.x + qv[2*j]);
                s1 += vv[2*j+1] * tanh_mufu(f1.y + qv[2*j+1]);
            }
#pragma unroll
            for (int j = 0; j < 4; j++) {
                float2 f0 = __half22float2(h0b[j]);
                float2 f1 = __half22float2(h1b[j]);
                s0 += vv[8+2*j]   * tanh_mufu(f0.x + qv[8+2*j]);
                s0 += vv[8+2*j+1] * tanh_mufu(f0.y + qv[8+2*j+1]);
                s1 += vv[8+2*j]   * tanh_mufu(f1.x + qv[8+2*j]);
                s1 += vv[8+2*j+1] * tanh_mufu(f1.y + qv[8+2*j+1]);
            }
#pragma unroll
            for (int off = 16; off; off >>= 1) {
                s0 += __shfl_xor_sync(0xffffffffu, s0, off);
                s1 += __shfl_xor_sync(0xffffffffu, s1, off);
            }
        }
        if (lane == 0) {
            float u0 = m0 ? __expf(s0) : 0.f;
            float u1 = m1 ? __expf(s1) : 0.f;
            g_ue[b * T_ + t0] = u0;
            if (t1 < T_) g_ue[b * T_ + t1] = u1;
            wsum += u0 + u1;
        }
    }
    if (lane == 0) wred[warp] = wsum;
    __syncthreads();
    if (tid == 0) {
        float s = 0.f;
#pragma unroll
        for (int i = 0; i < 8; i++) s += wred[i];
        g_epart[b * NEC + blockIdx.x] = s;
    }
}

// ---------------- per-step context (split-T, fp16 enc) + ws store ----------
// grid (NCC=12, B), 256 threads; thread handles half2 column pair a = 2*tid.
__global__ void __launch_bounds__(256) context_kernel(
        const int* __restrict__ enc_len,
        float* __restrict__ out_ws, int step) {
    int b = blockIdx.y, tc = blockIdx.x, tid = threadIdx.x;
    int len = enc_len[b];

    __shared__ float s_inv;
    __shared__ float w_s[128];
    if (tid == 0) {
        float s = 0.f;
#pragma unroll
        for (int i = 0; i < NEC; i++) s += g_epart[b * NEC + i];
        s_inv = 1.f / s;
    }
    __syncthreads();
    float inv = s_inv;

    int t0 = tc * 125;
    int t1 = t0 + 125;
    {
        int t = t0 + tid;
        float w = 0.f;
        if (tid < 125) {
            w = (t < len) ? g_ue[b * T_ + t] * inv : 0.f;
            if (out_ws) out_ws[((size_t)b * LQ + step) * T_ + t] = w;
            w_s[tid] = w;
        }
    }
    __syncthreads();

    int nt = min(t1, len) - t0;
    if (nt < 0) nt = 0;
    float acc0 = 0.f, acc1 = 0.f;
    const __half2* ep2 = (const __half2*)(&g_encH[((size_t)b * T_ + t0) * 512]) + tid;
    int ttm = nt & ~7;
    for (int tt = 0; tt < ttm; tt += 8) {
#pragma unroll
        for (int u = 0; u < 8; u++) {
            float w = w_s[tt + u];
            float2 f = __half22float2(__ldcs((const __half2*)(ep2 + (size_t)(tt + u) * 256)));
            acc0 += w * f.x;
            acc1 += w * f.y;
        }
    }
    for (int tt = ttm; tt < nt; tt++) {
        float w = w_s[tt];
        float2 f = __half22float2(__ldcs((const __half2*)(ep2 + (size_t)tt * 256)));
        acc0 += w * f.x;
        acc1 += w * f.y;
    }
    float* cp = &g_cpart[((size_t)tc * B_ + b) * A_];
    cp[2 * tid]     = acc0;
    cp[2 * tid + 1] = acc1;
}

// ---------------- final context reduce (step 100 only) ----------------
__global__ void __launch_bounds__(512) final_c_kernel(int step) {
    int b = blockIdx.x, a = threadIdx.x;
    float s = 0.f;
#pragma unroll
    for (int tc = 0; tc < NCC; tc++) s += g_cpart[((size_t)tc * B_ + b) * A_ + a];
    g_zc[((size_t)b * LQ + step) * 1024 + 512 + a] = s;
}

// ---------------- final epilogue: log_softmax gather + argmax ----------------
__global__ void __launch_bounds__(256) epilogue_kernel(const int* __restrict__ ys,
                                                       const float* __restrict__ logits,
                                                       float* __restrict__ out_ylp,
                                                       float* __restrict__ out_pred) {
    int m = blockIdx.x, tid = threadIdx.x;
    const float* row = logits + (size_t)m * V_;
    __shared__ float sv[256];
    __shared__ int si[256];
    float mx = -3.4e38f; int mi = 0;
    for (int v = tid; v < V_; v += 256) {
        float x = row[v];
        if (x > mx) { mx = x; mi = v; }
    }
    sv[tid] = mx; si[tid] = mi; __syncthreads();
    for (int off = 128; off; off >>= 1) {
        if (tid < off) {
            float xo = sv[tid + off]; int io = si[tid + off];
            if (xo > sv[tid] || (xo == sv[tid] && io < si[tid])) { sv[tid] = xo; si[tid] = io; }
        }
        __syncthreads();
    }
    mx = sv[0]; int argi = si[0]; __syncthreads();
    float s = 0.f;
    for (int v = tid; v < V_; v += 256) s += __expf(row[v] - mx);
    sv[tid] = s; __syncthreads();
    for (int off = 128; off; off >>= 1) {
        if (tid < off) sv[tid] += sv[tid + off];
        __syncthreads();
    }
    if (tid == 0) {
        int b = m / LQ, t = m % LQ;
        int yo = (t < 100) ? ys[b * 100 + t] : 2;   // EOS=2
        out_ylp[m]  = row[yo] - mx - logf(sv[0]);
        out_pred[m] = (float)argi;
    }
}

// ---------------- host launch ----------------
extern "C" void kernel_launch(void* const* d_in, const int* in_sizes, int n_in,
                              void* d_out, int out_size) {
    const float* enc_pad  = (const float*)d_in[0];
    const int*   enc_len  = (const int*)  d_in[1];
    const int*   ys       = (const int*)  d_in[2];
    const float* emb_tab  = (const float*)d_in[3];
    const float* W_ih     = (const float*)d_in[4];
    const float* W_hh     = (const float*)d_in[5];
    const float* b_ih     = (const float*)d_in[6];
    const float* b_hh     = (const float*)d_in[7];
    const float* W_enc    = (const float*)d_in[8];
    const float* W_dec    = (const float*)d_in[9];
    const float* v_att    = (const float*)d_in[10];
    const float* W_out    = (const float*)d_in[11];
    const float* b_out    = (const float*)d_in[12];
    (void)in_sizes; (void)n_in;

    float* out = (float*)d_out;
    const size_t n_logits = (size_t)B_ * LQ * V_;
    const size_t n_row    = (size_t)B_ * LQ;
    const size_t n_full   = n_logits + 2 * n_row + (size_t)B_ * LQ * T_;
    bool full = ((size_t)out_size >= n_full);

    float* out_logits = out;
    float* out_ylp  = full ? out + n_logits            : nullptr;
    float* out_pred = full ? out + n_logits + n_row    : nullptr;
    float* out_ws   = full ? out + n_logits + 2*n_row  : nullptr;

    float *pEmb, *pEmbG, *pZC, *pWencT, *pBias;
    __half* pPh;
    cudaGetSymbolAddress((void**)&pPh,    g_Ph);
    cudaGetSymbolAddress((void**)&pEmb,   g_emb);
    cudaGetSymbolAddress((void**)&pEmbG,  g_embg);
    cudaGetSymbolAddress((void**)&pZC,    g_zc);
    cudaGetSymbolAddress((void**)&pWencT, g_WencT);
    cudaGetSymbolAddress((void**)&pBias,  g_bias);

    // setup
    init_state_kernel<<<(NCC * B_ * A_ + 255) / 256, 256>>>();
    convert_enc_kernel<<<(B_ * T_ * A_ / 2 + 255) / 256, 256>>>(enc_pad);
    transpose_wenc_kernel<<<(512 * 512 + 255) / 256, 256>>>(W_enc);
    pack_wrec_kernel<<<(G4H * 1024 + 255) / 256, 256>>>(W_ih, W_hh, b_ih, b_hh);
    gather_emb_kernel<<<B_ * LQ, 128>>>(ys, emb_tab);

    // enc_proj = enc_pad @ W_enc  -> fp16
    {
        dim3 g((A_ + 127) / 128, (B_ * T_ + 127) / 128);
        sgemm_nt<__half><<<g, 256>>>(enc_pad, A_, pWencT, A_, nullptr, pPh, A_,
                                     B_ * T_, A_, A_);
    }
    // emb-part of gates (+combined bias)
    {
        dim3 g((G4H + 127) / 128, (B_ * LQ + 127) / 128);
        sgemm_nt<float><<<g, 256>>>(pEmb, E_, W_ih, E_ + A_, pBias, pEmbG, G4H,
                                    B_ * LQ, G4H, E_);
    }

    // sequential decode loop (4 kernels/step)
    for (int t = 0; t < LQ; t++) {
        gates_kernel<<<dim3(16, 8), 256>>>(t);
        lstm_pw_q_kernel<<<B_, 1024>>>(W_dec, t);
        attn_e_kernel<<<dim3(NEC, B_), 256>>>(enc_len, v_att);
        context_kernel<<<dim3(NCC, B_), 256>>>(enc_len, out_ws, t);
    }
    final_c_kernel<<<B_, 512>>>(LQ - 1);

    // logits = [dec_z | c] @ W_out^T + b_out
    {
        dim3 g((V_ + 127) / 128, (B_ * LQ + 127) / 128);
        sgemm_nt<float><<<g, 256>>>(pZC, H_ + A_, W_out, H_ + A_, b_out, out_logits, V_,
                                    B_ * LQ, V_, H_ + A_);
    }
    if (full) {
        epilogue_kernel<<<B_ * LQ, 256>>>(ys, out_logits, out_ylp, out_pred);
    }
}